// round 6
// baseline (speedup 1.0000x reference)
#include <cuda_runtime.h>
#include <cuda_bf16.h>
#include <math.h>
#include <stdint.h>

#define BSZ   32
#define TLEN  64
#define ED    512
#define HD    512
#define G4    2048
#define M2    2048
#define VOC   32000
#define RB    128

// ---------------- scratch (device globals; no allocation) ----------------
__device__ float g_xs [M2 * ED];
__device__ float g_pre[M2 * G4];
__device__ float g_y  [M2 * HD];     // unused now (kept for layout stability)
__device__ float g_u2 [M2 * HD];
__device__ float g_state[98304];
#define OFF_H0 0            // [2][16384]
#define OFF_C0 32768        // [16384]
#define OFF_H1 49152        // [2][16384]
#define OFF_C1 81920        // [16384]

__device__ unsigned g_flags[RB];

// ================= helpers =================
__device__ __forceinline__ uint32_t smem_u32(const void* p) {
    uint32_t a;
    asm("{ .reg .u64 t; cvta.to.shared.u64 t, %1; cvt.u32.u64 %0, t; }" : "=r"(a) : "l"(p));
    return a;
}
__device__ __forceinline__ float fsig(float x) {
    return __fdividef(1.f, 1.f + __expf(-x));
}
__device__ __forceinline__ float ftanh(float x) {
    return 1.f - __fdividef(2.f, __expf(2.f * x) + 1.f);
}

#define LDMX4(r0, r1, r2, r3, a) \
    asm volatile("ldmatrix.sync.aligned.m8n8.x4.shared.b16 {%0,%1,%2,%3}, [%4];" \
        : "=r"(r0), "=r"(r1), "=r"(r2), "=r"(r3) : "r"(a))

#define STS128(a, r0, r1, r2, r3) \
    asm volatile("st.shared.v4.b32 [%0], {%1,%2,%3,%4};" \
        :: "r"(a), "r"(r0), "r"(r1), "r"(r2), "r"(r3) : "memory")

__device__ __forceinline__ void mma16816(float* d, const uint32_t* a, const uint32_t* b) {
    asm volatile("mma.sync.aligned.m16n8k16.row.col.f32.bf16.bf16.f32 "
        "{%0,%1,%2,%3},{%4,%5,%6,%7},{%8,%9},{%0,%1,%2,%3};"
        : "+f"(d[0]), "+f"(d[1]), "+f"(d[2]), "+f"(d[3])
        : "r"(a[0]), "r"(a[1]), "r"(a[2]), "r"(a[3]), "r"(b[0]), "r"(b[1]));
}

__device__ __forceinline__ void cvt_hilo(const float4* v, uint32_t* h, uint32_t* l) {
    #pragma unroll
    for (int i = 0; i < 4; i++) {
        float a0 = v[i].x, a1 = v[i].y, a2 = v[i].z, a3 = v[i].w;
        uint32_t h0, h1, l0, l1;
        asm("cvt.rn.bf16x2.f32 %0, %1, %2;" : "=r"(h0) : "f"(a1), "f"(a0));
        asm("cvt.rn.bf16x2.f32 %0, %1, %2;" : "=r"(h1) : "f"(a3), "f"(a2));
        float r0 = a0 - __uint_as_float(h0 << 16);
        float r1 = a1 - __uint_as_float(h0 & 0xFFFF0000u);
        float r2 = a2 - __uint_as_float(h1 << 16);
        float r3 = a3 - __uint_as_float(h1 & 0xFFFF0000u);
        asm("cvt.rn.bf16x2.f32 %0, %1, %2;" : "=r"(l0) : "f"(r1), "f"(r0));
        asm("cvt.rn.bf16x2.f32 %0, %1, %2;" : "=r"(l1) : "f"(r3), "f"(r2));
        h[2*i] = h0; h[2*i+1] = h1; l[2*i] = l0; l[2*i+1] = l1;
    }
}

// ================= split-bf16 HMMA GEMM (known-good) ====
#define PADK   40
#define T_BH   20480
#define STAGE  40960
#define GSMEM  81920

__device__ __forceinline__ void stage_store(uint32_t base, const float4* v) {
    uint32_t h[8], l[8];
    cvt_hilo(v, h, l);
    STS128(base,              h[0], h[1], h[2], h[3]);
    STS128(base + 16,         h[4], h[5], h[6], h[7]);
    STS128(base + 10240,      l[0], l[1], l[2], l[3]);
    STS128(base + 10240 + 16, l[4], l[5], l[6], l[7]);
}

template<int PERM>
__global__ void __launch_bounds__(256, 1)
k_mmagemm(const float* __restrict__ X, const float* __restrict__ W,
          const float* __restrict__ bias, float* __restrict__ C, int ldc) {
    extern __shared__ char smx[];
    uint32_t sb = smem_u32(smx);
    int tid = threadIdx.x, lid = tid & 31, wid = tid >> 5;
    int wm = wid >> 2, wn = wid & 3;
    int rb = blockIdx.x * 128, cb = blockIdx.y * 128;

    int r = tid >> 1, kh = (tid & 1) * 16;
    const float4* xp = (const float4*)(X + (size_t)(rb + r) * 512 + kh);
    const float4* wp = (const float4*)(W + (size_t)(cb + r) * 512 + kh);
    uint32_t stb = sb + (uint32_t)(r * PADK + kh) * 2;

    float4 xr[4], wr[4];
    #pragma unroll
    for (int i = 0; i < 4; i++) { xr[i] = xp[i]; wr[i] = wp[i]; }
    stage_store(stb, xr);
    stage_store(stb + T_BH, wr);
    __syncthreads();

    uint32_t abase = sb + (uint32_t)((wm * 64 + (lid & 15)) * PADK + (lid >> 4) * 8) * 2;
    uint32_t bbase = sb + T_BH + (uint32_t)((wn * 32 + (lid & 15)) * PADK + (lid >> 4) * 8) * 2;

    float acc[4][4][4] = {};

    for (int c = 0; c < 16; c++) {
        if (c < 15) {
            #pragma unroll
            for (int i = 0; i < 4; i++) { xr[i] = xp[(c + 1) * 8 + i]; wr[i] = wp[(c + 1) * 8 + i]; }
        }
        uint32_t so = (uint32_t)(c & 1) * STAGE;
        #pragma unroll
        for (int ks = 0; ks < 2; ks++) {
            uint32_t ah[4][4], al[4][4], bh[4][2], bl[4][2];
            #pragma unroll
            for (int ma = 0; ma < 4; ma++) {
                uint32_t ad = abase + so + (uint32_t)(ma * 16 * PADK * 2 + ks * 32);
                LDMX4(ah[ma][0], ah[ma][1], ah[ma][2], ah[ma][3], ad);
                LDMX4(al[ma][0], al[ma][1], al[ma][2], al[ma][3], ad + 10240);
            }
            #pragma unroll
            for (int p = 0; p < 2; p++) {
                uint32_t bd = bbase + so + (uint32_t)(p * 16 * PADK * 2 + ks * 32);
                uint32_t m0, m1, m2, m3;
                LDMX4(m0, m1, m2, m3, bd);
                bh[2*p][0] = m0; bh[2*p][1] = m2; bh[2*p+1][0] = m1; bh[2*p+1][1] = m3;
                LDMX4(m0, m1, m2, m3, bd + 10240);
                bl[2*p][0] = m0; bl[2*p][1] = m2; bl[2*p+1][0] = m1; bl[2*p+1][1] = m3;
            }
            #pragma unroll
            for (int ma = 0; ma < 4; ma++)
                #pragma unroll
                for (int na = 0; na < 4; na++) {
                    mma16816(acc[ma][na], ah[ma], bh[na]);
                    mma16816(acc[ma][na], ah[ma], bl[na]);
                    mma16816(acc[ma][na], al[ma], bh[na]);
                }
        }
        if (c < 15) {
            uint32_t st2 = stb + (uint32_t)((c + 1) & 1) * STAGE;
            stage_store(st2, xr);
            stage_store(st2 + T_BH, wr);
        }
        __syncthreads();
    }

    #pragma unroll
    for (int ma = 0; ma < 4; ma++) {
        int m  = rb + wm * 64 + ma * 16 + (lid >> 2);
        int m2 = m + 8;
        size_t ro0 = PERM ? (size_t)((m  & 31) * TLEN + (m  >> 5)) : (size_t)m;
        size_t ro1 = PERM ? (size_t)((m2 & 31) * TLEN + (m2 >> 5)) : (size_t)m2;
        #pragma unroll
        for (int na = 0; na < 4; na++) {
            int c0 = cb + wn * 32 + na * 8 + (lid & 3) * 2;
            float2 bv = *(const float2*)(bias + c0);
            float* a = acc[ma][na];
            *(float2*)(C + ro0 * (size_t)ldc + c0) = make_float2(a[0] + bv.x, a[1] + bv.y);
            *(float2*)(C + ro1 * (size_t)ldc + c0) = make_float2(a[2] + bv.x, a[3] + bv.y);
        }
    }
}

// ---------------- zero state ----------------
__global__ void k_zero() {
    int i = blockIdx.x * 256 + threadIdx.x;
    ((float4*)g_state)[i] = make_float4(0.f, 0.f, 0.f, 0.f);
}

// ---------------- embedding gather ----------------
__global__ void k_embed(const int* __restrict__ toks, const int* __restrict__ tgt,
                        const float* __restrict__ emb, float* __restrict__ xs, int dec) {
    int row = blockIdx.x;
    int t = row >> 5, b = row & 31;
    int tok;
    if (dec) tok = (t == 0) ? 1 : tgt[b * TLEN + t - 1];
    else     tok = toks[b * TLEN + t];
    const float4* src = (const float4*)(emb + (size_t)tok * ED);
    float4*       dst = (float4*)(xs + (size_t)row * ED);
    dst[threadIdx.x] = src[threadIdx.x];
}

// ================= fused 2-layer wavefront recurrence =================
// Round tau in [0,65): layer0 computes step tau (tau<64), layer1 computes step
// tau-1 (tau>=1). Both depend only on round tau-1 outputs -> one global
// barrier per round; 65 rounds replace 128 steps + 1 input-GEMM launch.
// Layer1's gates = y0(t)@Wih1^T + h1(t-1)@Whh1^T + b1 computed in-round
// (K=1024 concat). Thread = (row r 0..15, K-slice ks 0..15), W in registers.
#define HSLICE 1032
#define P_STR  20
#define F_H0SM 0
#define F_H1SM 16512
#define F_PART 33024
#define F_GATE 43264
#define FSMEM  ((43264 + 512) * 4)    // 175,104 B

template<int STORE_Y>
__global__ void __launch_bounds__(256, 1)
k_fused(const float* __restrict__ pre0, const float* __restrict__ Whh0,
        const float* __restrict__ Wih1, const float* __restrict__ Whh1,
        const float* __restrict__ b1,
        float* __restrict__ h0buf, float* __restrict__ c0buf,
        float* __restrict__ h1buf, float* __restrict__ c1buf,
        float* __restrict__ yout) {
    extern __shared__ float sm[];
    float* h0sm = sm + F_H0SM;
    float* h1sm = sm + F_H1SM;
    float* part = sm + F_PART;
    float* gate = sm + F_GATE;

    int tid = threadIdx.x, bl = blockIdx.x;
    int w = tid >> 5, l = tid & 31;
    int ks = w * 2 + (l >> 4);
    int r  = l & 15;
    int col = (ks + r) & 15;
    int j = (r >> 2) * 512 + bl * 4 + (r & 3);

    // layer0 Whh slice (32 floats) in registers
    float4 w0reg[8];
    {
        const float4* s = (const float4*)(Whh0 + (size_t)j * 512 + ks * 32);
        #pragma unroll
        for (int i = 0; i < 8; i++) w0reg[i] = s[i];
    }
    // layer1 concat-W slice (64 floats): ks<8 -> Wih1, ks>=8 -> Whh1
    float4 w1reg[16];
    {
        const float* src = (ks < 8) ? (Wih1 + (size_t)j * 512 + (ks & 7) * 64)
                                    : (Whh1 + (size_t)j * 512 + (ks & 7) * 64);
        #pragma unroll
        for (int i = 0; i < 16; i++) w1reg[i] = ((const float4*)src)[i];
    }
    // layer1 h source slice base in smem
    float* hsl1 = ((ks < 8) ? h0sm : h1sm) + (ks & 7) * 2 * HSLICE;

    // reduction mapping
    int o0 = tid, o1 = tid + 256;
    int r0 = o0 >> 5, b0 = o0 & 31, r1 = o1 >> 5, b1_ = o1 & 31;
    int j0 = (r0 >> 2) * 512 + bl * 4 + (r0 & 3);
    int j1 = (r1 >> 2) * 512 + bl * 4 + (r1 & 3);
    float bias0 = b1[j0], bias1v = b1[j1];

    unsigned base = *((volatile unsigned*)&g_flags[bl]);

    int em0 = tid < 128, em1 = tid >= 128;
    int m_l = (tid >> 5) & 3, eb = tid & 31;
    int m_g = bl * 4 + m_l;
    float c0_reg = em0 ? c0buf[m_g * 32 + eb] : 0.f;
    float c1_reg = em1 ? c1buf[m_g * 32 + eb] : 0.f;

    for (int tau = 0; tau <= TLEN; tau++) {
        int doL0 = (tau < TLEN), doL1 = (tau >= 1);

        float pp0 = 0.f, pp1 = 0.f;
        if (doL0) {
            pp0 = pre0[(size_t)(tau * 32 + b0)  * G4 + j0];
            pp1 = pre0[(size_t)(tau * 32 + b1_) * G4 + j1];
        }

        // stage h0(tau-1) and h1(tau-2), both at slot tau&1
        {
            const float4* s0 = (const float4*)(h0buf + (tau & 1) * 16384);
            const float4* s1 = (const float4*)(h1buf + (tau & 1) * 16384);
            #pragma unroll
            for (int i = 0; i < 16; i++) {
                int lin = tid + i * 256;
                int k = lin >> 3, b4 = lin & 7;
                int off = (k >> 5) * HSLICE + (k & 31) * 32 + b4 * 4;
                float4 v0 = __ldcg(s0 + lin);
                *(float4*)(h0sm + off) = v0;
                float4 v1 = __ldcg(s1 + lin);
                *(float4*)(h1sm + off) = v1;
            }
        }
        __syncthreads();

        if (doL0) {
            float acc[32];
            #pragma unroll
            for (int i = 0; i < 32; i++) acc[i] = 0.f;
            const float4* hq = (const float4*)(h0sm + ks * HSLICE);
            const float*  wf = (const float*)w0reg;
            #pragma unroll 4
            for (int kl = 0; kl < 32; kl++) {
                float wv = wf[kl];
                #pragma unroll
                for (int q = 0; q < 8; q++) {
                    float4 h4 = hq[kl * 8 + q];
                    acc[q*4+0] = fmaf(wv, h4.x, acc[q*4+0]);
                    acc[q*4+1] = fmaf(wv, h4.y, acc[q*4+1]);
                    acc[q*4+2] = fmaf(wv, h4.z, acc[q*4+2]);
                    acc[q*4+3] = fmaf(wv, h4.w, acc[q*4+3]);
                }
            }
            #pragma unroll
            for (int b = 0; b < 32; b++)
                part[(r * 32 + b) * P_STR + col] = acc[b];
            __syncthreads();
            {
                const float4* p0 = (const float4*)(part + o0 * P_STR);
                const float4* p1 = (const float4*)(part + o1 * P_STR);
                float4 s0 = p0[0], s1 = p1[0];
                #pragma unroll
                for (int c = 1; c < 4; c++) {
                    float4 a = p0[c], b = p1[c];
                    s0.x += a.x; s0.y += a.y; s0.z += a.z; s0.w += a.w;
                    s1.x += b.x; s1.y += b.y; s1.z += b.z; s1.w += b.w;
                }
                gate[o0] = pp0 + s0.x + s0.y + s0.z + s0.w;
                gate[o1] = pp1 + s1.x + s1.y + s1.z + s1.w;
            }
            __syncthreads();
            if (em0) {
                float iv = gate[(0  + m_l) * 32 + eb];
                float fv = gate[(4  + m_l) * 32 + eb];
                float gv = gate[(8  + m_l) * 32 + eb];
                float ov = gate[(12 + m_l) * 32 + eb];
                c0_reg = fsig(fv) * c0_reg + fsig(iv) * ftanh(gv);
                float h = fsig(ov) * ftanh(c0_reg);
                h0buf[((tau + 1) & 1) * 16384 + m_g * 32 + eb] = h;
            }
            __syncthreads();
        }

        float h1v = 0.f;
        if (doL1) {
            float acc[32];
            #pragma unroll
            for (int i = 0; i < 32; i++) acc[i] = 0.f;
            const float4* hq0 = (const float4*)(hsl1);
            const float4* hq1 = (const float4*)(hsl1 + HSLICE);
            const float*  wf = (const float*)w1reg;
            #pragma unroll 4
            for (int kl = 0; kl < 32; kl++) {
                float wv = wf[kl];
                #pragma unroll
                for (int q = 0; q < 8; q++) {
                    float4 h4 = hq0[kl * 8 + q];
                    acc[q*4+0] = fmaf(wv, h4.x, acc[q*4+0]);
                    acc[q*4+1] = fmaf(wv, h4.y, acc[q*4+1]);
                    acc[q*4+2] = fmaf(wv, h4.z, acc[q*4+2]);
                    acc[q*4+3] = fmaf(wv, h4.w, acc[q*4+3]);
                }
            }
            #pragma unroll 4
            for (int kl = 0; kl < 32; kl++) {
                float wv = wf[32 + kl];
                #pragma unroll
                for (int q = 0; q < 8; q++) {
                    float4 h4 = hq1[kl * 8 + q];
                    acc[q*4+0] = fmaf(wv, h4.x, acc[q*4+0]);
                    acc[q*4+1] = fmaf(wv, h4.y, acc[q*4+1]);
                    acc[q*4+2] = fmaf(wv, h4.z, acc[q*4+2]);
                    acc[q*4+3] = fmaf(wv, h4.w, acc[q*4+3]);
                }
            }
            #pragma unroll
            for (int b = 0; b < 32; b++)
                part[(r * 32 + b) * P_STR + col] = acc[b];
            __syncthreads();
            {
                const float4* p0 = (const float4*)(part + o0 * P_STR);
                const float4* p1 = (const float4*)(part + o1 * P_STR);
                float4 s0 = p0[0], s1 = p1[0];
                #pragma unroll
                for (int c = 1; c < 4; c++) {
                    float4 a = p0[c], b = p1[c];
                    s0.x += a.x; s0.y += a.y; s0.z += a.z; s0.w += a.w;
                    s1.x += b.x; s1.y += b.y; s1.z += b.z; s1.w += b.w;
                }
                gate[o0] = bias0  + s0.x + s0.y + s0.z + s0.w;
                gate[o1] = bias1v + s1.x + s1.y + s1.z + s1.w;
            }
            __syncthreads();
            if (em1) {
                float iv = gate[(0  + m_l) * 32 + eb];
                float fv = gate[(4  + m_l) * 32 + eb];
                float gv = gate[(8  + m_l) * 32 + eb];
                float ov = gate[(12 + m_l) * 32 + eb];
                c1_reg = fsig(fv) * c1_reg + fsig(iv) * ftanh(gv);
                h1v = fsig(ov) * ftanh(c1_reg);
                h1buf[((tau - 1) & 1) * 16384 + m_g * 32 + eb] = h1v;
            }
        }
        __syncthreads();

        if (tid == 0)
            asm volatile("st.release.gpu.global.u32 [%0], %1;"
                :: "l"(g_flags + bl), "r"(base + tau + 1) : "memory");
        // y-output store AFTER the release: off the drain path; next-launch
        // visibility is guaranteed by the kernel boundary.
        if (STORE_Y && doL1 && em1)
            yout[(size_t)((tau - 1) * 32 + eb) * HD + m_g] = h1v;
        if (tid < 32) {
            unsigned tg = base + tau + 1;
            const unsigned* f = g_flags + tid * 4;
            for (;;) {
                unsigned v0, v1, v2, v3;
                asm volatile("ld.acquire.gpu.global.u32 %0, [%1];" : "=r"(v0) : "l"(f));
                asm volatile("ld.acquire.gpu.global.u32 %0, [%1];" : "=r"(v1) : "l"(f + 1));
                asm volatile("ld.acquire.gpu.global.u32 %0, [%1];" : "=r"(v2) : "l"(f + 2));
                asm volatile("ld.acquire.gpu.global.u32 %0, [%1];" : "=r"(v3) : "l"(f + 3));
                int ok = ((int)(v0 - tg) >= 0) & ((int)(v1 - tg) >= 0) &
                         ((int)(v2 - tg) >= 0) & ((int)(v3 - tg) >= 0);
                if (__all_sync(0xFFFFFFFFu, ok)) break;
            }
        }
        __syncthreads();
    }
    if (em0) c0buf[m_g * 32 + eb] = c0_reg;
    if (em1) c1buf[m_g * 32 + eb] = c1_reg;
}

// ---------------- launcher ----------------
extern "C" void kernel_launch(void* const* d_in, const int* in_sizes, int n_in,
                              void* d_out, int out_size) {
    const int*   x       = (const int*)  d_in[0];
    const int*   tgt     = (const int*)  d_in[1];
    const float* enc_emb = (const float*)d_in[2];
    const float* dec_emb = (const float*)d_in[3];
    const float* e0_Wih  = (const float*)d_in[4];
    const float* e0_Whh  = (const float*)d_in[5];
    const float* e0_b    = (const float*)d_in[6];
    const float* e1_Wih  = (const float*)d_in[7];
    const float* e1_Whh  = (const float*)d_in[8];
    const float* e1_b    = (const float*)d_in[9];
    const float* d0_Wih  = (const float*)d_in[10];
    const float* d0_Whh  = (const float*)d_in[11];
    const float* d0_b    = (const float*)d_in[12];
    const float* d1_Wih  = (const float*)d_in[13];
    const float* d1_Whh  = (const float*)d_in[14];
    const float* d1_b    = (const float*)d_in[15];
    const float* lin_W   = (const float*)d_in[16];
    const float* lin_b   = (const float*)d_in[17];
    float* out = (float*)d_out;

    float *xs, *pre, *u2, *st;
    cudaGetSymbolAddress((void**)&xs,  g_xs);
    cudaGetSymbolAddress((void**)&pre, g_pre);
    cudaGetSymbolAddress((void**)&u2,  g_u2);
    cudaGetSymbolAddress((void**)&st,  g_state);

    cudaFuncSetAttribute(k_fused<0>, cudaFuncAttributeMaxDynamicSharedMemorySize, FSMEM);
    cudaFuncSetAttribute(k_fused<1>, cudaFuncAttributeMaxDynamicSharedMemorySize, FSMEM);
    cudaFuncSetAttribute(k_mmagemm<0>, cudaFuncAttributeMaxDynamicSharedMemorySize, GSMEM);
    cudaFuncSetAttribute(k_mmagemm<1>, cudaFuncAttributeMaxDynamicSharedMemorySize, GSMEM);

    dim3 gg(16, 16), gp(16, VOC / 128);

    k_zero<<<96, 256>>>();

    // encoder: in-GEMM for layer0, then fused 2-layer wavefront
    k_embed<<<M2, 128>>>(x, tgt, enc_emb, xs, 0);
    k_mmagemm<0><<<gg, 256, GSMEM>>>(xs, e0_Wih, e0_b, pre, G4);
    k_fused<0><<<RB, 256, FSMEM>>>(pre, e0_Whh, e1_Wih, e1_Whh, e1_b,
                                   st + OFF_H0, st + OFF_C0,
                                   st + OFF_H1, st + OFF_C1, u2);

    // decoder
    k_embed<<<M2, 128>>>(x, tgt, dec_emb, xs, 1);
    k_mmagemm<0><<<gg, 256, GSMEM>>>(xs, d0_Wih, d0_b, pre, G4);
    k_fused<1><<<RB, 256, FSMEM>>>(pre, d0_Whh, d1_Wih, d1_Whh, d1_b,
                                   st + OFF_H0, st + OFF_C0,
                                   st + OFF_H1, st + OFF_C1, u2);

    // projection
    k_mmagemm<1><<<gp, 256, GSMEM>>>(u2, lin_W, lin_b, out, VOC);
}

// round 7
// speedup vs baseline: 1.5095x; 1.5095x over previous
#include <cuda_runtime.h>
#include <cuda_bf16.h>
#include <math.h>
#include <stdint.h>

#define BSZ   32
#define TLEN  64
#define ED    512
#define HD    512
#define G4    2048
#define M2    2048
#define VOC   32000
#define RB    128

// ---------------- scratch (device globals; no allocation) ----------------
__device__ float g_xs [M2 * ED];
__device__ float g_pre[M2 * G4];
__device__ float g_u2 [M2 * HD];
__device__ float g_state[98304];
#define OFF_H0 0            // [2][16384]
#define OFF_C0 32768        // [16384]
#define OFF_H1 49152        // [2][16384]
#define OFF_C1 81920        // [16384]

__device__ unsigned g_flags[RB];

// ================= helpers =================
__device__ __forceinline__ uint32_t smem_u32(const void* p) {
    uint32_t a;
    asm("{ .reg .u64 t; cvta.to.shared.u64 t, %1; cvt.u32.u64 %0, t; }" : "=r"(a) : "l"(p));
    return a;
}
__device__ __forceinline__ float fsig(float x) {
    return __fdividef(1.f, 1.f + __expf(-x));
}
__device__ __forceinline__ float ftanh(float x) {
    return 1.f - __fdividef(2.f, __expf(2.f * x) + 1.f);
}

#define LDMX4(r0, r1, r2, r3, a) \
    asm volatile("ldmatrix.sync.aligned.m8n8.x4.shared.b16 {%0,%1,%2,%3}, [%4];" \
        : "=r"(r0), "=r"(r1), "=r"(r2), "=r"(r3) : "r"(a))

#define STS128(a, r0, r1, r2, r3) \
    asm volatile("st.shared.v4.b32 [%0], {%1,%2,%3,%4};" \
        :: "r"(a), "r"(r0), "r"(r1), "r"(r2), "r"(r3) : "memory")

__device__ __forceinline__ void mma16816(float* d, const uint32_t* a, const uint32_t* b) {
    asm volatile("mma.sync.aligned.m16n8k16.row.col.f32.bf16.bf16.f32 "
        "{%0,%1,%2,%3},{%4,%5,%6,%7},{%8,%9},{%0,%1,%2,%3};"
        : "+f"(d[0]), "+f"(d[1]), "+f"(d[2]), "+f"(d[3])
        : "r"(a[0]), "r"(a[1]), "r"(a[2]), "r"(a[3]), "r"(b[0]), "r"(b[1]));
}

__device__ __forceinline__ void cvt_hilo(const float4* v, uint32_t* h, uint32_t* l) {
    #pragma unroll
    for (int i = 0; i < 4; i++) {
        float a0 = v[i].x, a1 = v[i].y, a2 = v[i].z, a3 = v[i].w;
        uint32_t h0, h1, l0, l1;
        asm("cvt.rn.bf16x2.f32 %0, %1, %2;" : "=r"(h0) : "f"(a1), "f"(a0));
        asm("cvt.rn.bf16x2.f32 %0, %1, %2;" : "=r"(h1) : "f"(a3), "f"(a2));
        float r0 = a0 - __uint_as_float(h0 << 16);
        float r1 = a1 - __uint_as_float(h0 & 0xFFFF0000u);
        float r2 = a2 - __uint_as_float(h1 << 16);
        float r3 = a3 - __uint_as_float(h1 & 0xFFFF0000u);
        asm("cvt.rn.bf16x2.f32 %0, %1, %2;" : "=r"(l0) : "f"(r1), "f"(r0));
        asm("cvt.rn.bf16x2.f32 %0, %1, %2;" : "=r"(l1) : "f"(r3), "f"(r2));
        h[2*i] = h0; h[2*i+1] = h1; l[2*i] = l0; l[2*i+1] = l1;
    }
}

// ================= split-bf16 HMMA GEMM (known-good) ====
#define PADK   40
#define T_BH   20480
#define STAGE  40960
#define GSMEM  81920

__device__ __forceinline__ void stage_store(uint32_t base, const float4* v) {
    uint32_t h[8], l[8];
    cvt_hilo(v, h, l);
    STS128(base,              h[0], h[1], h[2], h[3]);
    STS128(base + 16,         h[4], h[5], h[6], h[7]);
    STS128(base + 10240,      l[0], l[1], l[2], l[3]);
    STS128(base + 10240 + 16, l[4], l[5], l[6], l[7]);
}

template<int PERM>
__global__ void __launch_bounds__(256, 1)
k_mmagemm(const float* __restrict__ X, const float* __restrict__ W,
          const float* __restrict__ bias, float* __restrict__ C, int ldc) {
    extern __shared__ char smx[];
    uint32_t sb = smem_u32(smx);
    int tid = threadIdx.x, lid = tid & 31, wid = tid >> 5;
    int wm = wid >> 2, wn = wid & 3;
    int rb = blockIdx.x * 128, cb = blockIdx.y * 128;

    int r = tid >> 1, kh = (tid & 1) * 16;
    const float4* xp = (const float4*)(X + (size_t)(rb + r) * 512 + kh);
    const float4* wp = (const float4*)(W + (size_t)(cb + r) * 512 + kh);
    uint32_t stb = sb + (uint32_t)(r * PADK + kh) * 2;

    float4 xr[4], wr[4];
    #pragma unroll
    for (int i = 0; i < 4; i++) { xr[i] = xp[i]; wr[i] = wp[i]; }
    stage_store(stb, xr);
    stage_store(stb + T_BH, wr);
    __syncthreads();

    uint32_t abase = sb + (uint32_t)((wm * 64 + (lid & 15)) * PADK + (lid >> 4) * 8) * 2;
    uint32_t bbase = sb + T_BH + (uint32_t)((wn * 32 + (lid & 15)) * PADK + (lid >> 4) * 8) * 2;

    float acc[4][4][4] = {};

    for (int c = 0; c < 16; c++) {
        if (c < 15) {
            #pragma unroll
            for (int i = 0; i < 4; i++) { xr[i] = xp[(c + 1) * 8 + i]; wr[i] = wp[(c + 1) * 8 + i]; }
        }
        uint32_t so = (uint32_t)(c & 1) * STAGE;
        #pragma unroll
        for (int ks = 0; ks < 2; ks++) {
            uint32_t ah[4][4], al[4][4], bh[4][2], bl[4][2];
            #pragma unroll
            for (int ma = 0; ma < 4; ma++) {
                uint32_t ad = abase + so + (uint32_t)(ma * 16 * PADK * 2 + ks * 32);
                LDMX4(ah[ma][0], ah[ma][1], ah[ma][2], ah[ma][3], ad);
                LDMX4(al[ma][0], al[ma][1], al[ma][2], al[ma][3], ad + 10240);
            }
            #pragma unroll
            for (int p = 0; p < 2; p++) {
                uint32_t bd = bbase + so + (uint32_t)(p * 16 * PADK * 2 + ks * 32);
                uint32_t m0, m1, m2, m3;
                LDMX4(m0, m1, m2, m3, bd);
                bh[2*p][0] = m0; bh[2*p][1] = m2; bh[2*p+1][0] = m1; bh[2*p+1][1] = m3;
                LDMX4(m0, m1, m2, m3, bd + 10240);
                bl[2*p][0] = m0; bl[2*p][1] = m2; bl[2*p+1][0] = m1; bl[2*p+1][1] = m3;
            }
            #pragma unroll
            for (int ma = 0; ma < 4; ma++)
                #pragma unroll
                for (int na = 0; na < 4; na++) {
                    mma16816(acc[ma][na], ah[ma], bh[na]);
                    mma16816(acc[ma][na], ah[ma], bl[na]);
                    mma16816(acc[ma][na], al[ma], bh[na]);
                }
        }
        if (c < 15) {
            uint32_t st2 = stb + (uint32_t)((c + 1) & 1) * STAGE;
            stage_store(st2, xr);
            stage_store(st2 + T_BH, wr);
        }
        __syncthreads();
    }

    #pragma unroll
    for (int ma = 0; ma < 4; ma++) {
        int m  = rb + wm * 64 + ma * 16 + (lid >> 2);
        int m2 = m + 8;
        size_t ro0 = PERM ? (size_t)((m  & 31) * TLEN + (m  >> 5)) : (size_t)m;
        size_t ro1 = PERM ? (size_t)((m2 & 31) * TLEN + (m2 >> 5)) : (size_t)m2;
        #pragma unroll
        for (int na = 0; na < 4; na++) {
            int c0 = cb + wn * 32 + na * 8 + (lid & 3) * 2;
            float2 bv = *(const float2*)(bias + c0);
            float* a = acc[ma][na];
            *(float2*)(C + ro0 * (size_t)ldc + c0) = make_float2(a[0] + bv.x, a[1] + bv.y);
            *(float2*)(C + ro1 * (size_t)ldc + c0) = make_float2(a[2] + bv.x, a[3] + bv.y);
        }
    }
}

// ---------------- zero state ----------------
__global__ void k_zero() {
    int i = blockIdx.x * 256 + threadIdx.x;
    ((float4*)g_state)[i] = make_float4(0.f, 0.f, 0.f, 0.f);
}

// ---------------- embedding gather ----------------
__global__ void k_embed(const int* __restrict__ toks, const int* __restrict__ tgt,
                        const float* __restrict__ emb, float* __restrict__ xs, int dec) {
    int row = blockIdx.x;
    int t = row >> 5, b = row & 31;
    int tok;
    if (dec) tok = (t == 0) ? 1 : tgt[b * TLEN + t - 1];
    else     tok = toks[b * TLEN + t];
    const float4* src = (const float4*)(emb + (size_t)tok * ED);
    float4*       dst = (float4*)(xs + (size_t)row * ED);
    dst[threadIdx.x] = src[threadIdx.x];
}

// ================= fused wavefront recurrence v2: 3 parallel sections =====
// 384 threads = 3 sections x 128. Round tau: sec0 computes L0 step tau,
// sec1 computes Wih1 . h0(tau-1) (L1 input half), sec2 computes Whh1 . h1(tau-2)
// (L1 recurrent half). All three read only round-(tau-1) state -> parallel.
// Reduce fused with pointwise: each thread reduces the 4 gates of its own cell.
#define FT     384
#define SLCSZ  2056                     // 64*32 + 8 pad floats per K-slice
#define P_STR  12
#define F_H1   16448
#define F_PART 32896                    // 3 x 512*12
#define FSMEM  ((32896 + 18432) * 4)    // 205,312 B

template<int STORE_Y>
__global__ void __launch_bounds__(FT, 1)
k_fused(const float* __restrict__ pre0, const float* __restrict__ Whh0,
        const float* __restrict__ Wih1, const float* __restrict__ Whh1,
        const float* __restrict__ b1,
        float* __restrict__ h0buf, float* __restrict__ c0buf,
        float* __restrict__ h1buf, float* __restrict__ c1buf,
        float* __restrict__ yout) {
    extern __shared__ float sm[];
    float* h0sm = sm;
    float* h1sm = sm + F_H1;
    float* partb = sm + F_PART;

    int tid = threadIdx.x, bl = blockIdx.x;
    int sec = tid >> 7, stid = tid & 127;
    int r = stid & 15, ks = stid >> 4;          // row 0..15, K-slice 0..7 (64 K)
    int col = (ks + r) & 7;
    int j = (r >> 2) * 512 + bl * 4 + (r & 3);

    // section weight slice: 64 floats in registers
    const float* wbase = (sec == 0) ? Whh0 : (sec == 1) ? Wih1 : Whh1;
    float4 wreg[16];
    {
        const float4* s = (const float4*)(wbase + (size_t)j * 512 + ks * 64);
        #pragma unroll
        for (int i = 0; i < 16; i++) wreg[i] = s[i];
    }
    float* mypart = partb + sec * 6144;
    float* hsrc_sm = (sec == 2) ? h1sm : h0sm;

    // cell mapping for pointwise (sec0 -> layer0 cell, sec1 -> layer1 cell)
    int m_l = stid >> 5, eb = stid & 31;
    int m_g = bl * 4 + m_l;
    float bias1[4];
    #pragma unroll
    for (int g = 0; g < 4; g++) bias1[g] = b1[g * 512 + bl * 4 + m_l];

    unsigned base = *((volatile unsigned*)&g_flags[bl]);

    float c0_reg = (sec == 0) ? c0buf[m_g * 32 + eb] : 0.f;
    float c1_reg = (sec == 1) ? c1buf[m_g * 32 + eb] : 0.f;

    for (int tau = 0; tau <= TLEN; tau++) {
        int doL0 = (tau < TLEN), doL1 = (tau >= 1);

        // prefetch pre0 for sec0's 4 gates (independent of h)
        float pp[4];
        if (sec == 0 && doL0) {
            #pragma unroll
            for (int g = 0; g < 4; g++)
                pp[g] = pre0[(size_t)(tau * 32 + eb) * G4 + g * 512 + bl * 4 + m_l];
        }

        // stage h0(tau-1) [threads 0-255] and h1(tau-2) [threads 256-383]
        if (tid < 256) {
            const float4* s0 = (const float4*)(h0buf + (tau & 1) * 16384);
            #pragma unroll
            for (int i = 0; i < 16; i++) {
                int lin = tid + i * 256;
                int k = lin >> 3, b4 = lin & 7;
                float4 v = __ldcg(s0 + lin);
                *(float4*)(h0sm + (k >> 6) * SLCSZ + (k & 63) * 32 + b4 * 4) = v;
            }
        } else {
            int t2 = tid - 256;
            const float4* s1 = (const float4*)(h1buf + (tau & 1) * 16384);
            #pragma unroll
            for (int i = 0; i < 32; i++) {
                int lin = t2 + i * 128;
                int k = lin >> 3, b4 = lin & 7;
                float4 v = __ldcg(s1 + lin);
                *(float4*)(h1sm + (k >> 6) * SLCSZ + (k & 63) * 32 + b4 * 4) = v;
            }
        }
        __syncthreads();

        // parallel GEMM units
        int active = (sec == 0) ? doL0 : doL1;
        if (active) {
            float acc[32];
            #pragma unroll
            for (int i = 0; i < 32; i++) acc[i] = 0.f;
            const float4* hq = (const float4*)(hsrc_sm + ks * SLCSZ);
            const float*  wf = (const float*)wreg;
            #pragma unroll 4
            for (int kl = 0; kl < 64; kl++) {
                float wv = wf[kl];
                #pragma unroll
                for (int q = 0; q < 8; q++) {
                    float4 h4 = hq[kl * 8 + q];
                    acc[q*4+0] = fmaf(wv, h4.x, acc[q*4+0]);
                    acc[q*4+1] = fmaf(wv, h4.y, acc[q*4+1]);
                    acc[q*4+2] = fmaf(wv, h4.z, acc[q*4+2]);
                    acc[q*4+3] = fmaf(wv, h4.w, acc[q*4+3]);
                }
            }
            #pragma unroll
            for (int b = 0; b < 32; b++)
                mypart[(r * 32 + b) * P_STR + col] = acc[b];
        }
        __syncthreads();

        // fused reduce + pointwise (sec0: layer0 cell; sec1: layer1 cell)
        if (sec == 0 && doL0) {
            float gv4[4];
            #pragma unroll
            for (int g = 0; g < 4; g++) {
                int o = (g * 4 + m_l) * 32 + eb;
                float4 a = *(const float4*)(partb + o * P_STR);
                float4 b = *(const float4*)(partb + o * P_STR + 4);
                gv4[g] = pp[g] + a.x + a.y + a.z + a.w + b.x + b.y + b.z + b.w;
            }
            c0_reg = fsig(gv4[1]) * c0_reg + fsig(gv4[0]) * ftanh(gv4[2]);
            float h = fsig(gv4[3]) * ftanh(c0_reg);
            h0buf[((tau + 1) & 1) * 16384 + m_g * 32 + eb] = h;
        }
        float h1v = 0.f;
        if (sec == 1 && doL1) {
            float gv4[4];
            #pragma unroll
            for (int g = 0; g < 4; g++) {
                int o = (g * 4 + m_l) * 32 + eb;
                float4 a = *(const float4*)(partb + 6144 + o * P_STR);
                float4 b = *(const float4*)(partb + 6144 + o * P_STR + 4);
                float4 c = *(const float4*)(partb + 12288 + o * P_STR);
                float4 d = *(const float4*)(partb + 12288 + o * P_STR + 4);
                gv4[g] = bias1[g] + a.x + a.y + a.z + a.w + b.x + b.y + b.z + b.w
                                  + c.x + c.y + c.z + c.w + d.x + d.y + d.z + d.w;
            }
            c1_reg = fsig(gv4[1]) * c1_reg + fsig(gv4[0]) * ftanh(gv4[2]);
            h1v = fsig(gv4[3]) * ftanh(c1_reg);
            h1buf[((tau - 1) & 1) * 16384 + m_g * 32 + eb] = h1v;
        }
        __syncthreads();

        if (tid == 0)
            asm volatile("st.release.gpu.global.u32 [%0], %1;"
                :: "l"(g_flags + bl), "r"(base + tau + 1) : "memory");
        // y store after release: off the critical drain path
        if (STORE_Y && sec == 1 && doL1)
            yout[(size_t)((tau - 1) * 32 + eb) * HD + m_g] = h1v;
        if (tid < 32) {
            unsigned tg = base + tau + 1;
            const unsigned* f = g_flags + tid * 4;
            for (;;) {
                unsigned v0, v1, v2, v3;
                asm volatile("ld.acquire.gpu.global.u32 %0, [%1];" : "=r"(v0) : "l"(f));
                asm volatile("ld.acquire.gpu.global.u32 %0, [%1];" : "=r"(v1) : "l"(f + 1));
                asm volatile("ld.acquire.gpu.global.u32 %0, [%1];" : "=r"(v2) : "l"(f + 2));
                asm volatile("ld.acquire.gpu.global.u32 %0, [%1];" : "=r"(v3) : "l"(f + 3));
                int ok = ((int)(v0 - tg) >= 0) & ((int)(v1 - tg) >= 0) &
                         ((int)(v2 - tg) >= 0) & ((int)(v3 - tg) >= 0);
                if (__all_sync(0xFFFFFFFFu, ok)) break;
            }
        }
        __syncthreads();
    }
    if (sec == 0) c0buf[m_g * 32 + eb] = c0_reg;
    if (sec == 1) c1buf[m_g * 32 + eb] = c1_reg;
}

// ---------------- launcher ----------------
extern "C" void kernel_launch(void* const* d_in, const int* in_sizes, int n_in,
                              void* d_out, int out_size) {
    const int*   x       = (const int*)  d_in[0];
    const int*   tgt     = (const int*)  d_in[1];
    const float* enc_emb = (const float*)d_in[2];
    const float* dec_emb = (const float*)d_in[3];
    const float* e0_Wih  = (const float*)d_in[4];
    const float* e0_Whh  = (const float*)d_in[5];
    const float* e0_b    = (const float*)d_in[6];
    const float* e1_Wih  = (const float*)d_in[7];
    const float* e1_Whh  = (const float*)d_in[8];
    const float* e1_b    = (const float*)d_in[9];
    const float* d0_Wih  = (const float*)d_in[10];
    const float* d0_Whh  = (const float*)d_in[11];
    const float* d0_b    = (const float*)d_in[12];
    const float* d1_Wih  = (const float*)d_in[13];
    const float* d1_Whh  = (const float*)d_in[14];
    const float* d1_b    = (const float*)d_in[15];
    const float* lin_W   = (const float*)d_in[16];
    const float* lin_b   = (const float*)d_in[17];
    float* out = (float*)d_out;

    float *xs, *pre, *u2, *st;
    cudaGetSymbolAddress((void**)&xs,  g_xs);
    cudaGetSymbolAddress((void**)&pre, g_pre);
    cudaGetSymbolAddress((void**)&u2,  g_u2);
    cudaGetSymbolAddress((void**)&st,  g_state);

    cudaFuncSetAttribute(k_fused<0>, cudaFuncAttributeMaxDynamicSharedMemorySize, FSMEM);
    cudaFuncSetAttribute(k_fused<1>, cudaFuncAttributeMaxDynamicSharedMemorySize, FSMEM);
    cudaFuncSetAttribute(k_mmagemm<0>, cudaFuncAttributeMaxDynamicSharedMemorySize, GSMEM);
    cudaFuncSetAttribute(k_mmagemm<1>, cudaFuncAttributeMaxDynamicSharedMemorySize, GSMEM);

    dim3 gg(16, 16), gp(16, VOC / 128);

    k_zero<<<96, 256>>>();

    // encoder
    k_embed<<<M2, 128>>>(x, tgt, enc_emb, xs, 0);
    k_mmagemm<0><<<gg, 256, GSMEM>>>(xs, e0_Wih, e0_b, pre, G4);
    k_fused<0><<<RB, FT, FSMEM>>>(pre, e0_Whh, e1_Wih, e1_Whh, e1_b,
                                  st + OFF_H0, st + OFF_C0,
                                  st + OFF_H1, st + OFF_C1, u2);

    // decoder
    k_embed<<<M2, 128>>>(x, tgt, dec_emb, xs, 1);
    k_mmagemm<0><<<gg, 256, GSMEM>>>(xs, d0_Wih, d0_b, pre, G4);
    k_fused<1><<<RB, FT, FSMEM>>>(pre, d0_Whh, d1_Wih, d1_Whh, d1_b,
                                  st + OFF_H0, st + OFF_C0,
                                  st + OFF_H1, st + OFF_C1, u2);

    // projection
    k_mmagemm<1><<<gp, 256, GSMEM>>>(u2, lin_W, lin_b, out, VOC);
}

// round 8
// speedup vs baseline: 1.9529x; 1.2937x over previous
#include <cuda_runtime.h>
#include <cuda_bf16.h>
#include <math.h>
#include <stdint.h>

#define BSZ   32
#define TLEN  64
#define ED    512
#define HD    512
#define G4    2048
#define M2    2048
#define VOC   32000
#define RB    128

// ---------------- scratch (device globals; no allocation) ----------------
__device__ float g_xs [M2 * ED];
__device__ float g_pre[M2 * G4];
__device__ float g_u2 [M2 * HD];
__device__ float g_state[98304];
#define OFF_H0 0
#define OFF_C0 32768
#define OFF_H1 49152
#define OFF_C1 81920

__device__ unsigned g_flags[RB];

// ================= helpers =================
__device__ __forceinline__ uint32_t smem_u32(const void* p) {
    uint32_t a;
    asm("{ .reg .u64 t; cvta.to.shared.u64 t, %1; cvt.u32.u64 %0, t; }" : "=r"(a) : "l"(p));
    return a;
}
__device__ __forceinline__ float fsig(float x) {
    return __fdividef(1.f, 1.f + __expf(-x));
}
__device__ __forceinline__ float ftanh(float x) {
    return 1.f - __fdividef(2.f, __expf(2.f * x) + 1.f);
}

#define LDMX4(r0, r1, r2, r3, a) \
    asm volatile("ldmatrix.sync.aligned.m8n8.x4.shared.b16 {%0,%1,%2,%3}, [%4];" \
        : "=r"(r0), "=r"(r1), "=r"(r2), "=r"(r3) : "r"(a))

#define LDMX4T(r0, r1, r2, r3, a) \
    asm volatile("ldmatrix.sync.aligned.m8n8.x4.trans.shared.b16 {%0,%1,%2,%3}, [%4];" \
        : "=r"(r0), "=r"(r1), "=r"(r2), "=r"(r3) : "r"(a))

#define STS128(a, r0, r1, r2, r3) \
    asm volatile("st.shared.v4.b32 [%0], {%1,%2,%3,%4};" \
        :: "r"(a), "r"(r0), "r"(r1), "r"(r2), "r"(r3) : "memory")

#define STS64(a, r0, r1) \
    asm volatile("st.shared.v2.b32 [%0], {%1,%2};" \
        :: "r"(a), "r"(r0), "r"(r1) : "memory")

__device__ __forceinline__ void mma16816(float* d, const uint32_t* a, const uint32_t* b) {
    asm volatile("mma.sync.aligned.m16n8k16.row.col.f32.bf16.bf16.f32 "
        "{%0,%1,%2,%3},{%4,%5,%6,%7},{%8,%9},{%0,%1,%2,%3};"
        : "+f"(d[0]), "+f"(d[1]), "+f"(d[2]), "+f"(d[3])
        : "r"(a[0]), "r"(a[1]), "r"(a[2]), "r"(a[3]), "r"(b[0]), "r"(b[1]));
}

// float2 -> bf16x2 hi + bf16x2 lo-residual
__device__ __forceinline__ void cvt2(float x, float y, uint32_t& hi, uint32_t& lo) {
    asm("cvt.rn.bf16x2.f32 %0, %1, %2;" : "=r"(hi) : "f"(y), "f"(x));
    float rx = x - __uint_as_float(hi << 16);
    float ry = y - __uint_as_float(hi & 0xFFFF0000u);
    asm("cvt.rn.bf16x2.f32 %0, %1, %2;" : "=r"(lo) : "f"(ry), "f"(rx));
}

__device__ __forceinline__ void cvt_hilo(const float4* v, uint32_t* h, uint32_t* l) {
    #pragma unroll
    for (int i = 0; i < 4; i++) {
        cvt2(v[i].x, v[i].y, h[2*i],   l[2*i]);
        cvt2(v[i].z, v[i].w, h[2*i+1], l[2*i+1]);
    }
}

// ================= split-bf16 HMMA GEMM (known-good) ====
#define PADK   40
#define T_BH   20480
#define STAGE  40960
#define GSMEM  81920

__device__ __forceinline__ void stage_store(uint32_t base, const float4* v) {
    uint32_t h[8], l[8];
    cvt_hilo(v, h, l);
    STS128(base,              h[0], h[1], h[2], h[3]);
    STS128(base + 16,         h[4], h[5], h[6], h[7]);
    STS128(base + 10240,      l[0], l[1], l[2], l[3]);
    STS128(base + 10240 + 16, l[4], l[5], l[6], l[7]);
}

template<int PERM>
__global__ void __launch_bounds__(256, 1)
k_mmagemm(const float* __restrict__ X, const float* __restrict__ W,
          const float* __restrict__ bias, float* __restrict__ C, int ldc) {
    extern __shared__ char smx[];
    uint32_t sb = smem_u32(smx);
    int tid = threadIdx.x, lid = tid & 31, wid = tid >> 5;
    int wm = wid >> 2, wn = wid & 3;
    int rb = blockIdx.x * 128, cb = blockIdx.y * 128;

    int r = tid >> 1, kh = (tid & 1) * 16;
    const float4* xp = (const float4*)(X + (size_t)(rb + r) * 512 + kh);
    const float4* wp = (const float4*)(W + (size_t)(cb + r) * 512 + kh);
    uint32_t stb = sb + (uint32_t)(r * PADK + kh) * 2;

    float4 xr[4], wr[4];
    #pragma unroll
    for (int i = 0; i < 4; i++) { xr[i] = xp[i]; wr[i] = wp[i]; }
    stage_store(stb, xr);
    stage_store(stb + T_BH, wr);
    __syncthreads();

    uint32_t abase = sb + (uint32_t)((wm * 64 + (lid & 15)) * PADK + (lid >> 4) * 8) * 2;
    uint32_t bbase = sb + T_BH + (uint32_t)((wn * 32 + (lid & 15)) * PADK + (lid >> 4) * 8) * 2;

    float acc[4][4][4] = {};

    for (int c = 0; c < 16; c++) {
        if (c < 15) {
            #pragma unroll
            for (int i = 0; i < 4; i++) { xr[i] = xp[(c + 1) * 8 + i]; wr[i] = wp[(c + 1) * 8 + i]; }
        }
        uint32_t so = (uint32_t)(c & 1) * STAGE;
        #pragma unroll
        for (int ks = 0; ks < 2; ks++) {
            uint32_t ah[4][4], al[4][4], bh[4][2], bl[4][2];
            #pragma unroll
            for (int ma = 0; ma < 4; ma++) {
                uint32_t ad = abase + so + (uint32_t)(ma * 16 * PADK * 2 + ks * 32);
                LDMX4(ah[ma][0], ah[ma][1], ah[ma][2], ah[ma][3], ad);
                LDMX4(al[ma][0], al[ma][1], al[ma][2], al[ma][3], ad + 10240);
            }
            #pragma unroll
            for (int p = 0; p < 2; p++) {
                uint32_t bd = bbase + so + (uint32_t)(p * 16 * PADK * 2 + ks * 32);
                uint32_t m0, m1, m2, m3;
                LDMX4(m0, m1, m2, m3, bd);
                bh[2*p][0] = m0; bh[2*p][1] = m2; bh[2*p+1][0] = m1; bh[2*p+1][1] = m3;
                LDMX4(m0, m1, m2, m3, bd + 10240);
                bl[2*p][0] = m0; bl[2*p][1] = m2; bl[2*p+1][0] = m1; bl[2*p+1][1] = m3;
            }
            #pragma unroll
            for (int ma = 0; ma < 4; ma++)
                #pragma unroll
                for (int na = 0; na < 4; na++) {
                    mma16816(acc[ma][na], ah[ma], bh[na]);
                    mma16816(acc[ma][na], ah[ma], bl[na]);
                    mma16816(acc[ma][na], al[ma], bh[na]);
                }
        }
        if (c < 15) {
            uint32_t st2 = stb + (uint32_t)((c + 1) & 1) * STAGE;
            stage_store(st2, xr);
            stage_store(st2 + T_BH, wr);
        }
        __syncthreads();
    }

    #pragma unroll
    for (int ma = 0; ma < 4; ma++) {
        int m  = rb + wm * 64 + ma * 16 + (lid >> 2);
        int m2 = m + 8;
        size_t ro0 = PERM ? (size_t)((m  & 31) * TLEN + (m  >> 5)) : (size_t)m;
        size_t ro1 = PERM ? (size_t)((m2 & 31) * TLEN + (m2 >> 5)) : (size_t)m2;
        #pragma unroll
        for (int na = 0; na < 4; na++) {
            int c0 = cb + wn * 32 + na * 8 + (lid & 3) * 2;
            float2 bv = *(const float2*)(bias + c0);
            float* a = acc[ma][na];
            *(float2*)(C + ro0 * (size_t)ldc + c0) = make_float2(a[0] + bv.x, a[1] + bv.y);
            *(float2*)(C + ro1 * (size_t)ldc + c0) = make_float2(a[2] + bv.x, a[3] + bv.y);
        }
    }
}

// ---------------- zero state ----------------
__global__ void k_zero() {
    int i = blockIdx.x * 256 + threadIdx.x;
    ((float4*)g_state)[i] = make_float4(0.f, 0.f, 0.f, 0.f);
}

// ---------------- embedding gather ----------------
__global__ void k_embed(const int* __restrict__ toks, const int* __restrict__ tgt,
                        const float* __restrict__ emb, float* __restrict__ xs, int dec) {
    int row = blockIdx.x;
    int t = row >> 5, b = row & 31;
    int tok;
    if (dec) tok = (t == 0) ? 1 : tgt[b * TLEN + t - 1];
    else     tok = toks[b * TLEN + t];
    const float4* src = (const float4*)(emb + (size_t)tok * ED);
    float4*       dst = (float4*)(xs + (size_t)row * ED);
    dst[threadIdx.x] = src[threadIdx.x];
}

// ================= fused wavefront recurrence v3: HMMA units =================
// 384 threads = 3 sections x 4 warps. Section s computes one GEMM unit
// (s0: Whh0.h0 -> L0; s1: Wih1.h0, s2: Whh1.h1 -> L1) via mma.sync bf16
// split hi/lo. W fragments live in registers for all rounds; h is staged
// each round as bf16 hi/lo [k][40] (80B rows, ldmatrix.x4.trans friendly).
// Warp = one k-quarter (128 K); partials reduced via padded smem, fused
// with pointwise. One release/acquire flag barrier per round.
#define FT      384
#define HROW    80                     // bytes per h row (32 bf16 + 8 pad)
#define H0HI    0
#define H0LO    40960
#define H1HI    81920
#define H1LO    122880
#define PARTOFF 163840                 // bytes; floats idx 40960
#define PSTR    36                     // partial row stride (floats)
#define USTR    2304                   // unit stride in partials (4*16*36)
#define FSMEM   (163840 + 27648)       // 191,488 B

template<int STORE_Y>
__global__ void __launch_bounds__(FT, 1)
k_fused(const float* __restrict__ pre0, const float* __restrict__ Whh0,
        const float* __restrict__ Wih1, const float* __restrict__ Whh1,
        const float* __restrict__ b1,
        float* __restrict__ h0buf, float* __restrict__ c0buf,
        float* __restrict__ h1buf, float* __restrict__ c1buf,
        float* __restrict__ yout) {
    extern __shared__ char smc[];
    uint32_t sb = smem_u32(smc);
    float* part = (float*)(smc + PARTOFF);

    int tid = threadIdx.x, bl = blockIdx.x;
    int wid = tid >> 5, l = tid & 31;
    int sec = wid >> 2, kq = wid & 3;           // section 0..2, k-quarter 0..3

    // ---- one-time W fragment preload (A operand, m16k16 row-major) ----
    const float* wbase = (sec == 0) ? Whh0 : (sec == 1) ? Wih1 : Whh1;
    int rA = l >> 2, rB = rA + 8;               // fragment rows
    int jA = (rA >> 2) * 512 + bl * 4 + (rA & 3);
    int jB = (rB >> 2) * 512 + bl * 4 + (rB & 3);
    int kc = (l & 3) * 2;
    uint32_t ahi[8][4], alo[8][4];
    #pragma unroll
    for (int kt = 0; kt < 8; kt++) {
        int k0 = kq * 128 + kt * 16 + kc;
        float2 w00 = *(const float2*)(wbase + (size_t)jA * 512 + k0);
        float2 w10 = *(const float2*)(wbase + (size_t)jB * 512 + k0);
        float2 w01 = *(const float2*)(wbase + (size_t)jA * 512 + k0 + 8);
        float2 w11 = *(const float2*)(wbase + (size_t)jB * 512 + k0 + 8);
        cvt2(w00.x, w00.y, ahi[kt][0], alo[kt][0]);
        cvt2(w10.x, w10.y, ahi[kt][1], alo[kt][1]);
        cvt2(w01.x, w01.y, ahi[kt][2], alo[kt][2]);
        cvt2(w11.x, w11.y, ahi[kt][3], alo[kt][3]);
    }

    // ldmatrix.trans per-lane address components (B operand from h [k][n])
    int krow = (l & 7) + ((l & 8) ? 8 : 0);
    int ncol = (l & 16) ? 8 : 0;
    uint32_t hbase = sb + ((sec == 2) ? H1HI : H0HI)
                   + (uint32_t)(kq * 128 + krow) * HROW + ncol * 2;

    // partial slot for this warp
    float* myp = part + sec * USTR + kq * 576;

    // pointwise cell mapping (by 128-thread section position)
    int stid = tid & 127;
    int m_l = stid >> 5, eb = stid & 31;
    int m_g = bl * 4 + m_l;
    float bias1[4];
    #pragma unroll
    for (int g = 0; g < 4; g++) bias1[g] = b1[g * 512 + bl * 4 + m_l];

    unsigned base = *((volatile unsigned*)&g_flags[bl]);

    float c0_reg = (sec == 0) ? c0buf[m_g * 32 + eb] : 0.f;
    float c1_reg = (sec == 1) ? c1buf[m_g * 32 + eb] : 0.f;

    for (int tau = 0; tau <= TLEN; tau++) {
        int doL0 = (tau < TLEN), doL1 = (tau >= 1);

        // prefetch pre0 for sec0 pointwise (independent of h)
        float pp[4];
        if (sec == 0 && doL0) {
            #pragma unroll
            for (int g = 0; g < 4; g++)
                pp[g] = pre0[(size_t)(tau * 32 + eb) * G4 + g * 512 + bl * 4 + m_l];
        }

        // ---- stage h0(tau-1), h1(tau-2) as bf16 hi/lo [k][40] ----
        {
            const float4* s0 = (const float4*)(h0buf + (tau & 1) * 16384);
            const float4* s1 = (const float4*)(h1buf + (tau & 1) * 16384);
            #pragma unroll
            for (int i = 0; i < 22; i++) {
                int lin = tid + i * FT;
                if (lin < 8192) {
                    int which = lin >> 12;
                    int idx = lin & 4095;
                    int k = idx >> 3, b4 = idx & 7;
                    float4 v = __ldcg((which ? s1 : s0) + idx);
                    uint32_t h0p, h1p, l0p, l1p;
                    cvt2(v.x, v.y, h0p, l0p);
                    cvt2(v.z, v.w, h1p, l1p);
                    uint32_t ad = sb + (which ? H1HI : H0HI)
                                + (uint32_t)k * HROW + b4 * 8;
                    STS64(ad, h0p, h1p);
                    STS64(ad + 40960, l0p, l1p);
                }
            }
        }
        __syncthreads();

        // ---- HMMA unit: 8 k-tiles x (2 ldmx4.trans hi + 2 lo + 12 MMA) ----
        int active = (sec == 0) ? doL0 : doL1;
        if (active) {
            float acc[4][4];
            #pragma unroll
            for (int i = 0; i < 4; i++)
                #pragma unroll
                for (int q = 0; q < 4; q++) acc[i][q] = 0.f;
            #pragma unroll
            for (int kt = 0; kt < 8; kt++) {
                uint32_t ka = hbase + (uint32_t)(kt * 16) * HROW;
                uint32_t bh[4][2], bl2[4][2];
                #pragma unroll
                for (int nbp = 0; nbp < 2; nbp++) {
                    uint32_t m0, m1, m2, m3;
                    LDMX4T(m0, m1, m2, m3, ka + nbp * 32);
                    bh[2*nbp][0] = m0; bh[2*nbp][1] = m1;
                    bh[2*nbp+1][0] = m2; bh[2*nbp+1][1] = m3;
                    LDMX4T(m0, m1, m2, m3, ka + nbp * 32 + 40960);
                    bl2[2*nbp][0] = m0; bl2[2*nbp][1] = m1;
                    bl2[2*nbp+1][0] = m2; bl2[2*nbp+1][1] = m3;
                }
                #pragma unroll
                for (int nt = 0; nt < 4; nt++) {
                    mma16816(acc[nt], ahi[kt], bh[nt]);
                    mma16816(acc[nt], ahi[kt], bl2[nt]);
                    mma16816(acc[nt], alo[kt], bh[nt]);
                }
            }
            // store partials (rows rA, rB; padded stride -> conflict-free)
            #pragma unroll
            for (int nt = 0; nt < 4; nt++) {
                int c = nt * 8 + kc;
                *(float2*)(myp + rA * PSTR + c) = make_float2(acc[nt][0], acc[nt][1]);
                *(float2*)(myp + rB * PSTR + c) = make_float2(acc[nt][2], acc[nt][3]);
            }
        }
        __syncthreads();

        // ---- fused k-quarter reduce + pointwise ----
        if (sec == 0 && doL0) {
            float gv4[4];
            #pragma unroll
            for (int g = 0; g < 4; g++) {
                int o = (g * 4 + m_l) * PSTR + eb;
                gv4[g] = pp[g] + part[o] + part[576 + o] + part[1152 + o] + part[1728 + o];
            }
            c0_reg = fsig(gv4[1]) * c0_reg + fsig(gv4[0]) * ftanh(gv4[2]);
            float h = fsig(gv4[3]) * ftanh(c0_reg);
            h0buf[((tau + 1) & 1) * 16384 + m_g * 32 + eb] = h;
        }
        float h1v = 0.f;
        if (sec == 1 && doL1) {
            float gv4[4];
            #pragma unroll
            for (int g = 0; g < 4; g++) {
                int o = (g * 4 + m_l) * PSTR + eb;
                float s = bias1[g];
                #pragma unroll
                for (int w = 0; w < 4; w++)
                    s += part[USTR + w * 576 + o] + part[2 * USTR + w * 576 + o];
                gv4[g] = s;
            }
            c1_reg = fsig(gv4[1]) * c1_reg + fsig(gv4[0]) * ftanh(gv4[2]);
            h1v = fsig(gv4[3]) * ftanh(c1_reg);
            h1buf[((tau - 1) & 1) * 16384 + m_g * 32 + eb] = h1v;
        }
        __syncthreads();

        if (tid == 0)
            asm volatile("st.release.gpu.global.u32 [%0], %1;"
                :: "l"(g_flags + bl), "r"(base + tau + 1) : "memory");
        if (STORE_Y && sec == 1 && doL1)
            yout[(size_t)((tau - 1) * 32 + eb) * HD + m_g] = h1v;
        if (tid < 32) {
            unsigned tg = base + tau + 1;
            const unsigned* f = g_flags + tid * 4;
            for (;;) {
                unsigned v0, v1, v2, v3;
                asm volatile("ld.acquire.gpu.global.u32 %0, [%1];" : "=r"(v0) : "l"(f));
                asm volatile("ld.acquire.gpu.global.u32 %0, [%1];" : "=r"(v1) : "l"(f + 1));
                asm volatile("ld.acquire.gpu.global.u32 %0, [%1];" : "=r"(v2) : "l"(f + 2));
                asm volatile("ld.acquire.gpu.global.u32 %0, [%1];" : "=r"(v3) : "l"(f + 3));
                int ok = ((int)(v0 - tg) >= 0) & ((int)(v1 - tg) >= 0) &
                         ((int)(v2 - tg) >= 0) & ((int)(v3 - tg) >= 0);
                if (__all_sync(0xFFFFFFFFu, ok)) break;
            }
        }
        __syncthreads();
    }
    if (sec == 0) c0buf[m_g * 32 + eb] = c0_reg;
    if (sec == 1) c1buf[m_g * 32 + eb] = c1_reg;
}

// ---------------- launcher ----------------
extern "C" void kernel_launch(void* const* d_in, const int* in_sizes, int n_in,
                              void* d_out, int out_size) {
    const int*   x       = (const int*)  d_in[0];
    const int*   tgt     = (const int*)  d_in[1];
    const float* enc_emb = (const float*)d_in[2];
    const float* dec_emb = (const float*)d_in[3];
    const float* e0_Wih  = (const float*)d_in[4];
    const float* e0_Whh  = (const float*)d_in[5];
    const float* e0_b    = (const float*)d_in[6];
    const float* e1_Wih  = (const float*)d_in[7];
    const float* e1_Whh  = (const float*)d_in[8];
    const float* e1_b    = (const float*)d_in[9];
    const float* d0_Wih  = (const float*)d_in[10];
    const float* d0_Whh  = (const float*)d_in[11];
    const float* d0_b    = (const float*)d_in[12];
    const float* d1_Wih  = (const float*)d_in[13];
    const float* d1_Whh  = (const float*)d_in[14];
    const float* d1_b    = (const float*)d_in[15];
    const float* lin_W   = (const float*)d_in[16];
    const float* lin_b   = (const float*)d_in[17];
    float* out = (float*)d_out;

    float *xs, *pre, *u2, *st;
    cudaGetSymbolAddress((void**)&xs,  g_xs);
    cudaGetSymbolAddress((void**)&pre, g_pre);
    cudaGetSymbolAddress((void**)&u2,  g_u2);
    cudaGetSymbolAddress((void**)&st,  g_state);

    cudaFuncSetAttribute(k_fused<0>, cudaFuncAttributeMaxDynamicSharedMemorySize, FSMEM);
    cudaFuncSetAttribute(k_fused<1>, cudaFuncAttributeMaxDynamicSharedMemorySize, FSMEM);
    cudaFuncSetAttribute(k_mmagemm<0>, cudaFuncAttributeMaxDynamicSharedMemorySize, GSMEM);
    cudaFuncSetAttribute(k_mmagemm<1>, cudaFuncAttributeMaxDynamicSharedMemorySize, GSMEM);

    dim3 gg(16, 16), gp(16, VOC / 128);

    k_zero<<<96, 256>>>();

    // encoder
    k_embed<<<M2, 128>>>(x, tgt, enc_emb, xs, 0);
    k_mmagemm<0><<<gg, 256, GSMEM>>>(xs, e0_Wih, e0_b, pre, G4);
    k_fused<0><<<RB, FT, FSMEM>>>(pre, e0_Whh, e1_Wih, e1_Whh, e1_b,
                                  st + OFF_H0, st + OFF_C0,
                                  st + OFF_H1, st + OFF_C1, u2);

    // decoder
    k_embed<<<M2, 128>>>(x, tgt, dec_emb, xs, 1);
    k_mmagemm<0><<<gg, 256, GSMEM>>>(xs, d0_Wih, d0_b, pre, G4);
    k_fused<1><<<RB, FT, FSMEM>>>(pre, d0_Whh, d1_Wih, d1_Whh, d1_b,
                                  st + OFF_H0, st + OFF_C0,
                                  st + OFF_H1, st + OFF_C1, u2);

    // projection
    k_mmagemm<1><<<gp, 256, GSMEM>>>(u2, lin_W, lin_b, out, VOC);
}

// round 9
// speedup vs baseline: 2.2246x; 1.1392x over previous
#include <cuda_runtime.h>
#include <cuda_bf16.h>
#include <math.h>
#include <stdint.h>

#define BSZ   32
#define TLEN  64
#define ED    512
#define HD    512
#define G4    2048
#define M2    2048
#define VOC   32000
#define RB    128

// ---------------- scratch (device globals; no allocation) ----------------
__device__ float g_xs [M2 * ED];
__device__ float g_pre[M2 * G4];
__device__ float g_u2 [M2 * HD];
// h state, pre-converted bf16x2 planes: [layer][slot][plane hi/lo][512*16 u32]
__device__ uint32_t g_hq[2][2][2][8192];
__device__ float g_c[2][16384];       // c0, c1  [512][32]
__device__ __align__(16) unsigned g_flags[RB];

// ================= helpers =================
__device__ __forceinline__ uint32_t smem_u32(const void* p) {
    uint32_t a;
    asm("{ .reg .u64 t; cvta.to.shared.u64 t, %1; cvt.u32.u64 %0, t; }" : "=r"(a) : "l"(p));
    return a;
}
__device__ __forceinline__ float fsig(float x) {
    return __fdividef(1.f, 1.f + __expf(-x));
}
__device__ __forceinline__ float ftanh(float x) {
    return 1.f - __fdividef(2.f, __expf(2.f * x) + 1.f);
}

#define LDMX4(r0, r1, r2, r3, a) \
    asm volatile("ldmatrix.sync.aligned.m8n8.x4.shared.b16 {%0,%1,%2,%3}, [%4];" \
        : "=r"(r0), "=r"(r1), "=r"(r2), "=r"(r3) : "r"(a))

#define LDMX4T(r0, r1, r2, r3, a) \
    asm volatile("ldmatrix.sync.aligned.m8n8.x4.trans.shared.b16 {%0,%1,%2,%3}, [%4];" \
        : "=r"(r0), "=r"(r1), "=r"(r2), "=r"(r3) : "r"(a))

#define STS128(a, r0, r1, r2, r3) \
    asm volatile("st.shared.v4.b32 [%0], {%1,%2,%3,%4};" \
        :: "r"(a), "r"(r0), "r"(r1), "r"(r2), "r"(r3) : "memory")

__device__ __forceinline__ void mma16816(float* d, const uint32_t* a, const uint32_t* b) {
    asm volatile("mma.sync.aligned.m16n8k16.row.col.f32.bf16.bf16.f32 "
        "{%0,%1,%2,%3},{%4,%5,%6,%7},{%8,%9},{%0,%1,%2,%3};"
        : "+f"(d[0]), "+f"(d[1]), "+f"(d[2]), "+f"(d[3])
        : "r"(a[0]), "r"(a[1]), "r"(a[2]), "r"(a[3]), "r"(b[0]), "r"(b[1]));
}

// (x,y) -> bf16x2 hi word (x lower, y upper) + bf16x2 lo-residual word
__device__ __forceinline__ void cvt2(float x, float y, uint32_t& hi, uint32_t& lo) {
    asm("cvt.rn.bf16x2.f32 %0, %1, %2;" : "=r"(hi) : "f"(y), "f"(x));
    float rx = x - __uint_as_float(hi << 16);
    float ry = y - __uint_as_float(hi & 0xFFFF0000u);
    asm("cvt.rn.bf16x2.f32 %0, %1, %2;" : "=r"(lo) : "f"(ry), "f"(rx));
}

__device__ __forceinline__ void cvt_hilo(const float4* v, uint32_t* h, uint32_t* l) {
    #pragma unroll
    for (int i = 0; i < 4; i++) {
        cvt2(v[i].x, v[i].y, h[2*i],   l[2*i]);
        cvt2(v[i].z, v[i].w, h[2*i+1], l[2*i+1]);
    }
}

// ================= split-bf16 HMMA GEMM (known-good) ====
#define PADK   40
#define T_BH   20480
#define STAGE  40960
#define GSMEM  81920

__device__ __forceinline__ void stage_store(uint32_t base, const float4* v) {
    uint32_t h[8], l[8];
    cvt_hilo(v, h, l);
    STS128(base,              h[0], h[1], h[2], h[3]);
    STS128(base + 16,         h[4], h[5], h[6], h[7]);
    STS128(base + 10240,      l[0], l[1], l[2], l[3]);
    STS128(base + 10240 + 16, l[4], l[5], l[6], l[7]);
}

template<int PERM>
__global__ void __launch_bounds__(256, 1)
k_mmagemm(const float* __restrict__ X, const float* __restrict__ W,
          const float* __restrict__ bias, float* __restrict__ C, int ldc) {
    extern __shared__ char smx[];
    uint32_t sb = smem_u32(smx);
    int tid = threadIdx.x, lid = tid & 31, wid = tid >> 5;
    int wm = wid >> 2, wn = wid & 3;
    int rb = blockIdx.x * 128, cb = blockIdx.y * 128;

    int r = tid >> 1, kh = (tid & 1) * 16;
    const float4* xp = (const float4*)(X + (size_t)(rb + r) * 512 + kh);
    const float4* wp = (const float4*)(W + (size_t)(cb + r) * 512 + kh);
    uint32_t stb = sb + (uint32_t)(r * PADK + kh) * 2;

    float4 xr[4], wr[4];
    #pragma unroll
    for (int i = 0; i < 4; i++) { xr[i] = xp[i]; wr[i] = wp[i]; }
    stage_store(stb, xr);
    stage_store(stb + T_BH, wr);
    __syncthreads();

    uint32_t abase = sb + (uint32_t)((wm * 64 + (lid & 15)) * PADK + (lid >> 4) * 8) * 2;
    uint32_t bbase = sb + T_BH + (uint32_t)((wn * 32 + (lid & 15)) * PADK + (lid >> 4) * 8) * 2;

    float acc[4][4][4] = {};

    for (int c = 0; c < 16; c++) {
        if (c < 15) {
            #pragma unroll
            for (int i = 0; i < 4; i++) { xr[i] = xp[(c + 1) * 8 + i]; wr[i] = wp[(c + 1) * 8 + i]; }
        }
        uint32_t so = (uint32_t)(c & 1) * STAGE;
        #pragma unroll
        for (int ks = 0; ks < 2; ks++) {
            uint32_t ah[4][4], al[4][4], bh[4][2], bl[4][2];
            #pragma unroll
            for (int ma = 0; ma < 4; ma++) {
                uint32_t ad = abase + so + (uint32_t)(ma * 16 * PADK * 2 + ks * 32);
                LDMX4(ah[ma][0], ah[ma][1], ah[ma][2], ah[ma][3], ad);
                LDMX4(al[ma][0], al[ma][1], al[ma][2], al[ma][3], ad + 10240);
            }
            #pragma unroll
            for (int p = 0; p < 2; p++) {
                uint32_t bd = bbase + so + (uint32_t)(p * 16 * PADK * 2 + ks * 32);
                uint32_t m0, m1, m2, m3;
                LDMX4(m0, m1, m2, m3, bd);
                bh[2*p][0] = m0; bh[2*p][1] = m2; bh[2*p+1][0] = m1; bh[2*p+1][1] = m3;
                LDMX4(m0, m1, m2, m3, bd + 10240);
                bl[2*p][0] = m0; bl[2*p][1] = m2; bl[2*p+1][0] = m1; bl[2*p+1][1] = m3;
            }
            #pragma unroll
            for (int ma = 0; ma < 4; ma++)
                #pragma unroll
                for (int na = 0; na < 4; na++) {
                    mma16816(acc[ma][na], ah[ma], bh[na]);
                    mma16816(acc[ma][na], ah[ma], bl[na]);
                    mma16816(acc[ma][na], al[ma], bh[na]);
                }
        }
        if (c < 15) {
            uint32_t st2 = stb + (uint32_t)((c + 1) & 1) * STAGE;
            stage_store(st2, xr);
            stage_store(st2 + T_BH, wr);
        }
        __syncthreads();
    }

    #pragma unroll
    for (int ma = 0; ma < 4; ma++) {
        int m  = rb + wm * 64 + ma * 16 + (lid >> 2);
        int m2 = m + 8;
        size_t ro0 = PERM ? (size_t)((m  & 31) * TLEN + (m  >> 5)) : (size_t)m;
        size_t ro1 = PERM ? (size_t)((m2 & 31) * TLEN + (m2 >> 5)) : (size_t)m2;
        #pragma unroll
        for (int na = 0; na < 4; na++) {
            int c0 = cb + wn * 32 + na * 8 + (lid & 3) * 2;
            float2 bv = *(const float2*)(bias + c0);
            float* a = acc[ma][na];
            *(float2*)(C + ro0 * (size_t)ldc + c0) = make_float2(a[0] + bv.x, a[1] + bv.y);
            *(float2*)(C + ro1 * (size_t)ldc + c0) = make_float2(a[2] + bv.x, a[3] + bv.y);
        }
    }
}

// ---------------- zero state ----------------
__global__ void k_zero() {
    int i = blockIdx.x * 256 + threadIdx.x;      // 96*256 = 24576
    if (i < 16384) ((uint4*)g_hq)[i] = make_uint4(0u, 0u, 0u, 0u);
    else ((float4*)g_c)[i - 16384] = make_float4(0.f, 0.f, 0.f, 0.f);
}

// ---------------- embedding gather ----------------
__global__ void k_embed(const int* __restrict__ toks, const int* __restrict__ tgt,
                        const float* __restrict__ emb, float* __restrict__ xs, int dec) {
    int row = blockIdx.x;
    int t = row >> 5, b = row & 31;
    int tok;
    if (dec) tok = (t == 0) ? 1 : tgt[b * TLEN + t - 1];
    else     tok = toks[b * TLEN + t];
    const float4* src = (const float4*)(emb + (size_t)tok * ED);
    float4*       dst = (float4*)(xs + (size_t)row * ED);
    dst[threadIdx.x] = src[threadIdx.x];
}

// ================= fused wavefront recurrence v4 =================
// As R8 (HMMA units, 3 sections x 4 warps) but h lives in global ALREADY
// CONVERTED to bf16x2 hi/lo planes (producer-side cvt). Staging is a pure
// LDG.128->STS.128 copy. Flag poll is one v4 acquire load per lane.
#define FT      384
#define HROW    80
#define PARTOFF 163840
#define PSTR    36
#define USTR    2304
#define FSMEM   (163840 + 27648)

template<int STORE_Y>
__global__ void __launch_bounds__(FT, 1)
k_fused(const float* __restrict__ pre0, const float* __restrict__ Whh0,
        const float* __restrict__ Wih1, const float* __restrict__ Whh1,
        const float* __restrict__ b1,
        float* __restrict__ c0buf, float* __restrict__ c1buf,
        float* __restrict__ yout) {
    extern __shared__ char smc[];
    uint32_t sb = smem_u32(smc);
    float* part = (float*)(smc + PARTOFF);

    int tid = threadIdx.x, bl = blockIdx.x;
    int wid = tid >> 5, l = tid & 31;
    int sec = wid >> 2, kq = wid & 3;

    // ---- one-time W fragment preload ----
    const float* wbase = (sec == 0) ? Whh0 : (sec == 1) ? Wih1 : Whh1;
    int rA = l >> 2, rB = rA + 8;
    int jA = (rA >> 2) * 512 + bl * 4 + (rA & 3);
    int jB = (rB >> 2) * 512 + bl * 4 + (rB & 3);
    int kc = (l & 3) * 2;
    uint32_t ahi[8][4], alo[8][4];
    #pragma unroll
    for (int kt = 0; kt < 8; kt++) {
        int k0 = kq * 128 + kt * 16 + kc;
        float2 w00 = *(const float2*)(wbase + (size_t)jA * 512 + k0);
        float2 w10 = *(const float2*)(wbase + (size_t)jB * 512 + k0);
        float2 w01 = *(const float2*)(wbase + (size_t)jA * 512 + k0 + 8);
        float2 w11 = *(const float2*)(wbase + (size_t)jB * 512 + k0 + 8);
        cvt2(w00.x, w00.y, ahi[kt][0], alo[kt][0]);
        cvt2(w10.x, w10.y, ahi[kt][1], alo[kt][1]);
        cvt2(w01.x, w01.y, ahi[kt][2], alo[kt][2]);
        cvt2(w11.x, w11.y, ahi[kt][3], alo[kt][3]);
    }

    // ldmatrix.trans per-lane address (B operand from h [k][40B rows])
    int krow = (l & 7) + ((l & 8) ? 8 : 0);
    int ncol = (l & 16) ? 8 : 0;
    uint32_t hbase = sb + ((sec == 2) ? 81920u : 0u)
                   + (uint32_t)(kq * 128 + krow) * HROW + ncol * 2;

    float* myp = part + sec * USTR + kq * 576;

    int stid = tid & 127;
    int m_l = stid >> 5, eb = stid & 31;
    int m_g = bl * 4 + m_l;
    float bias1[4];
    #pragma unroll
    for (int g = 0; g < 4; g++) bias1[g] = b1[g * 512 + bl * 4 + m_l];

    unsigned base = *((volatile unsigned*)&g_flags[bl]);

    float c0_reg = (sec == 0) ? c0buf[m_g * 32 + eb] : 0.f;
    float c1_reg = (sec == 1) ? c1buf[m_g * 32 + eb] : 0.f;

    for (int tau = 0; tau <= TLEN; tau++) {
        int doL0 = (tau < TLEN), doL1 = (tau >= 1);

        float pp[4];
        if (sec == 0 && doL0) {
            #pragma unroll
            for (int g = 0; g < 4; g++)
                pp[g] = pre0[(size_t)(tau * 32 + eb) * G4 + g * 512 + bl * 4 + m_l];
        }

        // ---- stage h planes: pure uint4 copy (no conversion) ----
        {
            const uint4* s0 = (const uint4*)(&g_hq[0][tau & 1][0][0]);
            const uint4* s1 = (const uint4*)(&g_hq[1][tau & 1][0][0]);
            #pragma unroll
            for (int i = 0; i < 22; i++) {
                int lin = tid + i * FT;
                if (lin < 8192) {
                    uint4 v = __ldcg((lin < 4096 ? s0 : s1) + (lin & 4095));
                    uint32_t ad = sb + (uint32_t)(lin >> 11) * 40960u
                                + (uint32_t)((lin & 2047) >> 2) * HROW
                                + (uint32_t)(lin & 3) * 16u;
                    STS128(ad, v.x, v.y, v.z, v.w);
                }
            }
        }
        __syncthreads();

        // ---- HMMA unit ----
        int active = (sec == 0) ? doL0 : doL1;
        if (active) {
            float acc[4][4];
            #pragma unroll
            for (int i = 0; i < 4; i++)
                #pragma unroll
                for (int q = 0; q < 4; q++) acc[i][q] = 0.f;
            #pragma unroll
            for (int kt = 0; kt < 8; kt++) {
                uint32_t ka = hbase + (uint32_t)(kt * 16) * HROW;
                uint32_t bh[4][2], bl2[4][2];
                #pragma unroll
                for (int nbp = 0; nbp < 2; nbp++) {
                    uint32_t m0, m1, m2, m3;
                    LDMX4T(m0, m1, m2, m3, ka + nbp * 32);
                    bh[2*nbp][0] = m0; bh[2*nbp][1] = m1;
                    bh[2*nbp+1][0] = m2; bh[2*nbp+1][1] = m3;
                    LDMX4T(m0, m1, m2, m3, ka + nbp * 32 + 40960);
                    bl2[2*nbp][0] = m0; bl2[2*nbp][1] = m1;
                    bl2[2*nbp+1][0] = m2; bl2[2*nbp+1][1] = m3;
                }
                #pragma unroll
                for (int nt = 0; nt < 4; nt++) {
                    mma16816(acc[nt], ahi[kt], bh[nt]);
                    mma16816(acc[nt], ahi[kt], bl2[nt]);
                    mma16816(acc[nt], alo[kt], bh[nt]);
                }
            }
            #pragma unroll
            for (int nt = 0; nt < 4; nt++) {
                int c = nt * 8 + kc;
                *(float2*)(myp + rA * PSTR + c) = make_float2(acc[nt][0], acc[nt][1]);
                *(float2*)(myp + rB * PSTR + c) = make_float2(acc[nt][2], acc[nt][3]);
            }
        }
        __syncthreads();

        // ---- fused reduce + pointwise + producer-side bf16 pack ----
        if (sec == 0 && doL0) {
            float gv4[4];
            #pragma unroll
            for (int g = 0; g < 4; g++) {
                int o = (g * 4 + m_l) * PSTR + eb;
                gv4[g] = pp[g] + part[o] + part[576 + o] + part[1152 + o] + part[1728 + o];
            }
            c0_reg = fsig(gv4[1]) * c0_reg + fsig(gv4[0]) * ftanh(gv4[2]);
            float h = fsig(gv4[3]) * ftanh(c0_reg);
            float hot = __shfl_xor_sync(0xFFFFFFFFu, h, 1);
            if (!(eb & 1)) {
                uint32_t hi, lo;
                cvt2(h, hot, hi, lo);
                int idx = m_g * 16 + (eb >> 1);
                g_hq[0][(tau + 1) & 1][0][idx] = hi;
                g_hq[0][(tau + 1) & 1][1][idx] = lo;
            }
        }
        float h1v = 0.f;
        if (sec == 1 && doL1) {
            float gv4[4];
            #pragma unroll
            for (int g = 0; g < 4; g++) {
                int o = (g * 4 + m_l) * PSTR + eb;
                float s = bias1[g];
                #pragma unroll
                for (int w = 0; w < 4; w++)
                    s += part[USTR + w * 576 + o] + part[2 * USTR + w * 576 + o];
                gv4[g] = s;
            }
            c1_reg = fsig(gv4[1]) * c1_reg + fsig(gv4[0]) * ftanh(gv4[2]);
            h1v = fsig(gv4[3]) * ftanh(c1_reg);
            float hot = __shfl_xor_sync(0xFFFFFFFFu, h1v, 1);
            if (!(eb & 1)) {
                uint32_t hi, lo;
                cvt2(h1v, hot, hi, lo);
                int idx = m_g * 16 + (eb >> 1);
                g_hq[1][(tau - 1) & 1][0][idx] = hi;
                g_hq[1][(tau - 1) & 1][1][idx] = lo;
            }
        }
        __syncthreads();

        if (tid == 0)
            asm volatile("st.release.gpu.global.u32 [%0], %1;"
                :: "l"(g_flags + bl), "r"(base + tau + 1) : "memory");
        if (STORE_Y && sec == 1 && doL1)
            yout[(size_t)((tau - 1) * 32 + eb) * HD + m_g] = h1v;
        if (tid < 32) {
            unsigned tg = base + tau + 1;
            const unsigned* f = g_flags + tid * 4;
            for (;;) {
                unsigned v0, v1, v2, v3;
                asm volatile("ld.acquire.gpu.global.v4.u32 {%0,%1,%2,%3}, [%4];"
                    : "=r"(v0), "=r"(v1), "=r"(v2), "=r"(v3) : "l"(f));
                int ok = ((int)(v0 - tg) >= 0) & ((int)(v1 - tg) >= 0) &
                         ((int)(v2 - tg) >= 0) & ((int)(v3 - tg) >= 0);
                if (__all_sync(0xFFFFFFFFu, ok)) break;
            }
        }
        __syncthreads();
    }
    if (sec == 0) c0buf[m_g * 32 + eb] = c0_reg;
    if (sec == 1) c1buf[m_g * 32 + eb] = c1_reg;
}

// ---------------- launcher ----------------
extern "C" void kernel_launch(void* const* d_in, const int* in_sizes, int n_in,
                              void* d_out, int out_size) {
    const int*   x       = (const int*)  d_in[0];
    const int*   tgt     = (const int*)  d_in[1];
    const float* enc_emb = (const float*)d_in[2];
    const float* dec_emb = (const float*)d_in[3];
    const float* e0_Wih  = (const float*)d_in[4];
    const float* e0_Whh  = (const float*)d_in[5];
    const float* e0_b    = (const float*)d_in[6];
    const float* e1_Wih  = (const float*)d_in[7];
    const float* e1_Whh  = (const float*)d_in[8];
    const float* e1_b    = (const float*)d_in[9];
    const float* d0_Wih  = (const float*)d_in[10];
    const float* d0_Whh  = (const float*)d_in[11];
    const float* d0_b    = (const float*)d_in[12];
    const float* d1_Wih  = (const float*)d_in[13];
    const float* d1_Whh  = (const float*)d_in[14];
    const float* d1_b    = (const float*)d_in[15];
    const float* lin_W   = (const float*)d_in[16];
    const float* lin_b   = (const float*)d_in[17];
    float* out = (float*)d_out;

    float *xs, *pre, *u2, *cc;
    cudaGetSymbolAddress((void**)&xs,  g_xs);
    cudaGetSymbolAddress((void**)&pre, g_pre);
    cudaGetSymbolAddress((void**)&u2,  g_u2);
    cudaGetSymbolAddress((void**)&cc,  g_c);

    cudaFuncSetAttribute(k_fused<0>, cudaFuncAttributeMaxDynamicSharedMemorySize, FSMEM);
    cudaFuncSetAttribute(k_fused<1>, cudaFuncAttributeMaxDynamicSharedMemorySize, FSMEM);
    cudaFuncSetAttribute(k_mmagemm<0>, cudaFuncAttributeMaxDynamicSharedMemorySize, GSMEM);
    cudaFuncSetAttribute(k_mmagemm<1>, cudaFuncAttributeMaxDynamicSharedMemorySize, GSMEM);

    dim3 gg(16, 16), gp(16, VOC / 128);

    k_zero<<<96, 256>>>();

    // encoder
    k_embed<<<M2, 128>>>(x, tgt, enc_emb, xs, 0);
    k_mmagemm<0><<<gg, 256, GSMEM>>>(xs, e0_Wih, e0_b, pre, G4);
    k_fused<0><<<RB, FT, FSMEM>>>(pre, e0_Whh, e1_Wih, e1_Whh, e1_b,
                                  cc, cc + 16384, u2);

    // decoder
    k_embed<<<M2, 128>>>(x, tgt, dec_emb, xs, 1);
    k_mmagemm<0><<<gg, 256, GSMEM>>>(xs, d0_Wih, d0_b, pre, G4);
    k_fused<1><<<RB, FT, FSMEM>>>(pre, d0_Whh, d1_Wih, d1_Whh, d1_b,
                                  cc, cc + 16384, u2);

    // projection
    k_mmagemm<1><<<gp, 256, GSMEM>>>(u2, lin_W, lin_b, out, VOC);
}

// round 10
// speedup vs baseline: 2.9628x; 1.3318x over previous
#include <cuda_runtime.h>
#include <cuda_bf16.h>
#include <math.h>
#include <stdint.h>

#define BSZ   32
#define TLEN  64
#define ED    512
#define HD    512
#define G4    2048
#define M2    2048
#define VOC   32000
#define RB    128

// ---------------- scratch (device globals; no allocation) ----------------
__device__ float g_xs  [M2 * ED];
__device__ float g_preE[M2 * G4];
__device__ float g_preD[M2 * G4];
__device__ float g_u2  [M2 * HD];
// h state, pre-converted bf16x2 planes: [layer][slot][plane hi/lo][8192 u32]
__device__ uint32_t g_hq[2][2][2][8192];
__device__ __align__(16) unsigned g_flags2[RB * 32];   // one 128B line per flag

// ================= helpers =================
__device__ __forceinline__ uint32_t smem_u32(const void* p) {
    uint32_t a;
    asm("{ .reg .u64 t; cvta.to.shared.u64 t, %1; cvt.u32.u64 %0, t; }" : "=r"(a) : "l"(p));
    return a;
}
__device__ __forceinline__ float fsig(float x) {
    return __fdividef(1.f, 1.f + __expf(-x));
}
__device__ __forceinline__ float ftanh(float x) {
    return 1.f - __fdividef(2.f, __expf(2.f * x) + 1.f);
}

#define LDMX4(r0, r1, r2, r3, a) \
    asm volatile("ldmatrix.sync.aligned.m8n8.x4.shared.b16 {%0,%1,%2,%3}, [%4];" \
        : "=r"(r0), "=r"(r1), "=r"(r2), "=r"(r3) : "r"(a))

#define LDMX4T(r0, r1, r2, r3, a) \
    asm volatile("ldmatrix.sync.aligned.m8n8.x4.trans.shared.b16 {%0,%1,%2,%3}, [%4];" \
        : "=r"(r0), "=r"(r1), "=r"(r2), "=r"(r3) : "r"(a))

#define STS128(a, r0, r1, r2, r3) \
    asm volatile("st.shared.v4.b32 [%0], {%1,%2,%3,%4};" \
        :: "r"(a), "r"(r0), "r"(r1), "r"(r2), "r"(r3) : "memory")

__device__ __forceinline__ void mma16816(float* d, const uint32_t* a, const uint32_t* b) {
    asm volatile("mma.sync.aligned.m16n8k16.row.col.f32.bf16.bf16.f32 "
        "{%0,%1,%2,%3},{%4,%5,%6,%7},{%8,%9},{%0,%1,%2,%3};"
        : "+f"(d[0]), "+f"(d[1]), "+f"(d[2]), "+f"(d[3])
        : "r"(a[0]), "r"(a[1]), "r"(a[2]), "r"(a[3]), "r"(b[0]), "r"(b[1]));
}

__device__ __forceinline__ void cvt2(float x, float y, uint32_t& hi, uint32_t& lo) {
    asm("cvt.rn.bf16x2.f32 %0, %1, %2;" : "=r"(hi) : "f"(y), "f"(x));
    float rx = x - __uint_as_float(hi << 16);
    float ry = y - __uint_as_float(hi & 0xFFFF0000u);
    asm("cvt.rn.bf16x2.f32 %0, %1, %2;" : "=r"(lo) : "f"(ry), "f"(rx));
}

__device__ __forceinline__ void cvt_hilo(const float4* v, uint32_t* h, uint32_t* l) {
    #pragma unroll
    for (int i = 0; i < 4; i++) {
        cvt2(v[i].x, v[i].y, h[2*i],   l[2*i]);
        cvt2(v[i].z, v[i].w, h[2*i+1], l[2*i+1]);
    }
}

// ================= split-bf16 HMMA GEMM (known-good) ====
#define PADK   40
#define T_BH   20480
#define STAGE  40960
#define GSMEM  81920

__device__ __forceinline__ void stage_store(uint32_t base, const float4* v) {
    uint32_t h[8], l[8];
    cvt_hilo(v, h, l);
    STS128(base,              h[0], h[1], h[2], h[3]);
    STS128(base + 16,         h[4], h[5], h[6], h[7]);
    STS128(base + 10240,      l[0], l[1], l[2], l[3]);
    STS128(base + 10240 + 16, l[4], l[5], l[6], l[7]);
}

template<int PERM>
__global__ void __launch_bounds__(256, 1)
k_mmagemm(const float* __restrict__ X, const float* __restrict__ W,
          const float* __restrict__ bias, float* __restrict__ C, int ldc) {
    extern __shared__ char smx[];
    uint32_t sb = smem_u32(smx);
    int tid = threadIdx.x, lid = tid & 31, wid = tid >> 5;
    int wm = wid >> 2, wn = wid & 3;
    int rb = blockIdx.x * 128, cb = blockIdx.y * 128;

    int r = tid >> 1, kh = (tid & 1) * 16;
    const float4* xp = (const float4*)(X + (size_t)(rb + r) * 512 + kh);
    const float4* wp = (const float4*)(W + (size_t)(cb + r) * 512 + kh);
    uint32_t stb = sb + (uint32_t)(r * PADK + kh) * 2;

    float4 xr[4], wr[4];
    #pragma unroll
    for (int i = 0; i < 4; i++) { xr[i] = xp[i]; wr[i] = wp[i]; }
    stage_store(stb, xr);
    stage_store(stb + T_BH, wr);
    __syncthreads();

    uint32_t abase = sb + (uint32_t)((wm * 64 + (lid & 15)) * PADK + (lid >> 4) * 8) * 2;
    uint32_t bbase = sb + T_BH + (uint32_t)((wn * 32 + (lid & 15)) * PADK + (lid >> 4) * 8) * 2;

    float acc[4][4][4] = {};

    for (int c = 0; c < 16; c++) {
        if (c < 15) {
            #pragma unroll
            for (int i = 0; i < 4; i++) { xr[i] = xp[(c + 1) * 8 + i]; wr[i] = wp[(c + 1) * 8 + i]; }
        }
        uint32_t so = (uint32_t)(c & 1) * STAGE;
        #pragma unroll
        for (int ks = 0; ks < 2; ks++) {
            uint32_t ah[4][4], al[4][4], bh[4][2], bl[4][2];
            #pragma unroll
            for (int ma = 0; ma < 4; ma++) {
                uint32_t ad = abase + so + (uint32_t)(ma * 16 * PADK * 2 + ks * 32);
                LDMX4(ah[ma][0], ah[ma][1], ah[ma][2], ah[ma][3], ad);
                LDMX4(al[ma][0], al[ma][1], al[ma][2], al[ma][3], ad + 10240);
            }
            #pragma unroll
            for (int p = 0; p < 2; p++) {
                uint32_t bd = bbase + so + (uint32_t)(p * 16 * PADK * 2 + ks * 32);
                uint32_t m0, m1, m2, m3;
                LDMX4(m0, m1, m2, m3, bd);
                bh[2*p][0] = m0; bh[2*p][1] = m2; bh[2*p+1][0] = m1; bh[2*p+1][1] = m3;
                LDMX4(m0, m1, m2, m3, bd + 10240);
                bl[2*p][0] = m0; bl[2*p][1] = m2; bl[2*p+1][0] = m1; bl[2*p+1][1] = m3;
            }
            #pragma unroll
            for (int ma = 0; ma < 4; ma++)
                #pragma unroll
                for (int na = 0; na < 4; na++) {
                    mma16816(acc[ma][na], ah[ma], bh[na]);
                    mma16816(acc[ma][na], ah[ma], bl[na]);
                    mma16816(acc[ma][na], al[ma], bh[na]);
                }
        }
        if (c < 15) {
            uint32_t st2 = stb + (uint32_t)((c + 1) & 1) * STAGE;
            stage_store(st2, xr);
            stage_store(st2 + T_BH, wr);
        }
        __syncthreads();
    }

    #pragma unroll
    for (int ma = 0; ma < 4; ma++) {
        int m  = rb + wm * 64 + ma * 16 + (lid >> 2);
        int m2 = m + 8;
        size_t ro0 = PERM ? (size_t)((m  & 31) * TLEN + (m  >> 5)) : (size_t)m;
        size_t ro1 = PERM ? (size_t)((m2 & 31) * TLEN + (m2 >> 5)) : (size_t)m2;
        #pragma unroll
        for (int na = 0; na < 4; na++) {
            int c0 = cb + wn * 32 + na * 8 + (lid & 3) * 2;
            float2 bv = *(const float2*)(bias + c0);
            float* a = acc[ma][na];
            *(float2*)(C + ro0 * (size_t)ldc + c0) = make_float2(a[0] + bv.x, a[1] + bv.y);
            *(float2*)(C + ro1 * (size_t)ldc + c0) = make_float2(a[2] + bv.x, a[3] + bv.y);
        }
    }
}

// ---------------- zero h state ----------------
__global__ void k_zero() {
    int i = blockIdx.x * 256 + threadIdx.x;      // 64*256 = 16384 uint4
    ((uint4*)g_hq)[i] = make_uint4(0u, 0u, 0u, 0u);
}

// ---------------- embedding gather ----------------
__global__ void k_embed(const int* __restrict__ toks, const int* __restrict__ tgt,
                        const float* __restrict__ emb, float* __restrict__ xs, int dec) {
    int row = blockIdx.x;
    int t = row >> 5, b = row & 31;
    int tok;
    if (dec) tok = (t == 0) ? 1 : tgt[b * TLEN + t - 1];
    else     tok = toks[b * TLEN + t];
    const float4* src = (const float4*)(emb + (size_t)tok * ED);
    float4*       dst = (float4*)(xs + (size_t)row * ED);
    dst[threadIdx.x] = src[threadIdx.x];
}

// ================= merged 129-round enc+dec wavefront =================
// L0 active tau in [0,128): enc steps 0..63 (tau<64), dec steps 0..63 (tau>=64,
// weights/pre switch at tau=64; c continues in registers across the boundary).
// L1 active tau in [1,129): enc (tau<65), dec (tau>=65). Slot parity lines up
// exactly (L0 writes slot (tau+1)&1, L1 reads slot tau&1). d-weight fragments
// reloaded during the tau=63/64 poll wait. Flags: one 128B line per block.
#define FT      384
#define HROW    80
#define PARTOFF 163840
#define PSTR    36
#define USTR    2304
#define FSMEM   (163840 + 27648)

__device__ __forceinline__ void load_wfrag(const float* wbase, int jA, int jB,
                                           int kq, int kc,
                                           uint32_t ahi[8][4], uint32_t alo[8][4]) {
    #pragma unroll
    for (int kt = 0; kt < 8; kt++) {
        int k0 = kq * 128 + kt * 16 + kc;
        float2 w00 = *(const float2*)(wbase + (size_t)jA * 512 + k0);
        float2 w10 = *(const float2*)(wbase + (size_t)jB * 512 + k0);
        float2 w01 = *(const float2*)(wbase + (size_t)jA * 512 + k0 + 8);
        float2 w11 = *(const float2*)(wbase + (size_t)jB * 512 + k0 + 8);
        cvt2(w00.x, w00.y, ahi[kt][0], alo[kt][0]);
        cvt2(w10.x, w10.y, ahi[kt][1], alo[kt][1]);
        cvt2(w01.x, w01.y, ahi[kt][2], alo[kt][2]);
        cvt2(w11.x, w11.y, ahi[kt][3], alo[kt][3]);
    }
}

__global__ void __launch_bounds__(FT, 1)
k_merged(const float* __restrict__ preE, const float* __restrict__ preD,
         const float* __restrict__ e0_Whh, const float* __restrict__ e1_Wih,
         const float* __restrict__ e1_Whh, const float* __restrict__ e1_b,
         const float* __restrict__ d0_Whh, const float* __restrict__ d1_Wih,
         const float* __restrict__ d1_Whh, const float* __restrict__ d1_b,
         float* __restrict__ yout) {
    extern __shared__ char smc[];
    uint32_t sb = smem_u32(smc);
    float* part = (float*)(smc + PARTOFF);

    int tid = threadIdx.x, bl = blockIdx.x;
    int wid = tid >> 5, l = tid & 31;
    int sec = wid >> 2, kq = wid & 3;

    const float* w_e = (sec == 0) ? e0_Whh : (sec == 1) ? e1_Wih : e1_Whh;
    const float* w_d = (sec == 0) ? d0_Whh : (sec == 1) ? d1_Wih : d1_Whh;
    int wswitch = (sec == 0) ? 64 : 65;

    int rA = l >> 2, rB = rA + 8;
    int jA = (rA >> 2) * 512 + bl * 4 + (rA & 3);
    int jB = (rB >> 2) * 512 + bl * 4 + (rB & 3);
    int kc = (l & 3) * 2;
    uint32_t ahi[8][4], alo[8][4];
    load_wfrag(w_e, jA, jB, kq, kc, ahi, alo);

    int krow = (l & 7) + ((l & 8) ? 8 : 0);
    int ncol = (l & 16) ? 8 : 0;
    uint32_t hbase = sb + ((sec == 2) ? 81920u : 0u)
                   + (uint32_t)(kq * 128 + krow) * HROW + ncol * 2;

    float* myp = part + sec * USTR + kq * 576;

    int stid = tid & 127;
    int m_l = stid >> 5, eb = stid & 31;
    int m_g = bl * 4 + m_l;
    float biasE[4], biasD[4];
    #pragma unroll
    for (int g = 0; g < 4; g++) {
        biasE[g] = e1_b[g * 512 + bl * 4 + m_l];
        biasD[g] = d1_b[g * 512 + bl * 4 + m_l];
    }

    unsigned base = *((volatile unsigned*)&g_flags2[bl * 32]);

    float c0_reg = 0.f, c1_reg = 0.f;   // enc starts from zero state

    for (int tau = 0; tau <= 2 * TLEN; tau++) {
        int doL0 = (tau < 2 * TLEN), doL1 = (tau >= 1);

        float pp[4];
        if (sec == 0 && doL0) {
            const float* p = (tau < 64) ? preE : preD;
            int step = (tau < 64) ? tau : tau - 64;
            #pragma unroll
            for (int g = 0; g < 4; g++)
                pp[g] = p[(size_t)(step * 32 + eb) * G4 + g * 512 + bl * 4 + m_l];
        }

        // ---- stage h planes: pure uint4 copy ----
        {
            const uint4* s0 = (const uint4*)(&g_hq[0][tau & 1][0][0]);
            const uint4* s1 = (const uint4*)(&g_hq[1][tau & 1][0][0]);
            #pragma unroll
            for (int i = 0; i < 22; i++) {
                int lin = tid + i * FT;
                if (lin < 8192) {
                    uint4 v = __ldcg((lin < 4096 ? s0 : s1) + (lin & 4095));
                    uint32_t ad = sb + (uint32_t)(lin >> 11) * 40960u
                                + (uint32_t)((lin & 2047) >> 2) * HROW
                                + (uint32_t)(lin & 3) * 16u;
                    STS128(ad, v.x, v.y, v.z, v.w);
                }
            }
        }
        __syncthreads();

        // ---- HMMA unit ----
        int active = (sec == 0) ? doL0 : doL1;
        if (active) {
            float acc[4][4];
            #pragma unroll
            for (int i = 0; i < 4; i++)
                #pragma unroll
                for (int q = 0; q < 4; q++) acc[i][q] = 0.f;
            #pragma unroll
            for (int kt = 0; kt < 8; kt++) {
                uint32_t ka = hbase + (uint32_t)(kt * 16) * HROW;
                uint32_t bh[4][2], bl2[4][2];
                #pragma unroll
                for (int nbp = 0; nbp < 2; nbp++) {
                    uint32_t m0, m1, m2, m3;
                    LDMX4T(m0, m1, m2, m3, ka + nbp * 32);
                    bh[2*nbp][0] = m0; bh[2*nbp][1] = m1;
                    bh[2*nbp+1][0] = m2; bh[2*nbp+1][1] = m3;
                    LDMX4T(m0, m1, m2, m3, ka + nbp * 32 + 40960);
                    bl2[2*nbp][0] = m0; bl2[2*nbp][1] = m1;
                    bl2[2*nbp+1][0] = m2; bl2[2*nbp+1][1] = m3;
                }
                #pragma unroll
                for (int nt = 0; nt < 4; nt++) {
                    mma16816(acc[nt], ahi[kt], bh[nt]);
                    mma16816(acc[nt], ahi[kt], bl2[nt]);
                    mma16816(acc[nt], alo[kt], bh[nt]);
                }
            }
            #pragma unroll
            for (int nt = 0; nt < 4; nt++) {
                int c = nt * 8 + kc;
                *(float2*)(myp + rA * PSTR + c) = make_float2(acc[nt][0], acc[nt][1]);
                *(float2*)(myp + rB * PSTR + c) = make_float2(acc[nt][2], acc[nt][3]);
            }
        }
        __syncthreads();

        // ---- fused reduce + pointwise + producer-side bf16 pack ----
        if (sec == 0 && doL0) {
            float gv4[4];
            #pragma unroll
            for (int g = 0; g < 4; g++) {
                int o = (g * 4 + m_l) * PSTR + eb;
                gv4[g] = pp[g] + part[o] + part[576 + o] + part[1152 + o] + part[1728 + o];
            }
            c0_reg = fsig(gv4[1]) * c0_reg + fsig(gv4[0]) * ftanh(gv4[2]);
            float h = fsig(gv4[3]) * ftanh(c0_reg);
            float hot = __shfl_xor_sync(0xFFFFFFFFu, h, 1);
            if (!(eb & 1)) {
                uint32_t hi, lo;
                cvt2(h, hot, hi, lo);
                int idx = m_g * 16 + (eb >> 1);
                g_hq[0][(tau + 1) & 1][0][idx] = hi;
                g_hq[0][(tau + 1) & 1][1][idx] = lo;
            }
        }
        float h1v = 0.f;
        if (sec == 1 && doL1) {
            float gv4[4];
            #pragma unroll
            for (int g = 0; g < 4; g++) {
                int o = (g * 4 + m_l) * PSTR + eb;
                float s = (tau >= 65) ? biasD[g] : biasE[g];
                #pragma unroll
                for (int w = 0; w < 4; w++)
                    s += part[USTR + w * 576 + o] + part[2 * USTR + w * 576 + o];
                gv4[g] = s;
            }
            c1_reg = fsig(gv4[1]) * c1_reg + fsig(gv4[0]) * ftanh(gv4[2]);
            h1v = fsig(gv4[3]) * ftanh(c1_reg);
            float hot = __shfl_xor_sync(0xFFFFFFFFu, h1v, 1);
            if (!(eb & 1)) {
                uint32_t hi, lo;
                cvt2(h1v, hot, hi, lo);
                int idx = m_g * 16 + (eb >> 1);
                g_hq[1][(tau - 1) & 1][0][idx] = hi;
                g_hq[1][(tau - 1) & 1][1][idx] = lo;
            }
        }
        __syncthreads();

        if (tid == 0)
            asm volatile("st.release.gpu.global.u32 [%0], %1;"
                :: "l"(g_flags2 + bl * 32), "r"(base + tau + 1) : "memory");
        // off-critical-path work during barrier: y store + d-weight reload
        if (sec == 1 && tau >= 65)
            yout[(size_t)((tau - 65) * 32 + eb) * HD + m_g] = h1v;
        if (tau + 1 == wswitch)
            load_wfrag(w_d, jA, jB, kq, kc, ahi, alo);
        if (tid < 32) {
            unsigned tg = base + tau + 1;
            for (;;) {
                unsigned v0, v1, v2, v3;
                asm volatile("ld.acquire.gpu.global.u32 %0, [%1];" : "=r"(v0)
                    : "l"(g_flags2 + l * 32));
                asm volatile("ld.acquire.gpu.global.u32 %0, [%1];" : "=r"(v1)
                    : "l"(g_flags2 + (l + 32) * 32));
                asm volatile("ld.acquire.gpu.global.u32 %0, [%1];" : "=r"(v2)
                    : "l"(g_flags2 + (l + 64) * 32));
                asm volatile("ld.acquire.gpu.global.u32 %0, [%1];" : "=r"(v3)
                    : "l"(g_flags2 + (l + 96) * 32));
                int ok = ((int)(v0 - tg) >= 0) & ((int)(v1 - tg) >= 0) &
                         ((int)(v2 - tg) >= 0) & ((int)(v3 - tg) >= 0);
                if (__all_sync(0xFFFFFFFFu, ok)) break;
            }
        }
        __syncthreads();
    }
}

// ---------------- launcher ----------------
extern "C" void kernel_launch(void* const* d_in, const int* in_sizes, int n_in,
                              void* d_out, int out_size) {
    const int*   x       = (const int*)  d_in[0];
    const int*   tgt     = (const int*)  d_in[1];
    const float* enc_emb = (const float*)d_in[2];
    const float* dec_emb = (const float*)d_in[3];
    const float* e0_Wih  = (const float*)d_in[4];
    const float* e0_Whh  = (const float*)d_in[5];
    const float* e0_b    = (const float*)d_in[6];
    const float* e1_Wih  = (const float*)d_in[7];
    const float* e1_Whh  = (const float*)d_in[8];
    const float* e1_b    = (const float*)d_in[9];
    const float* d0_Wih  = (const float*)d_in[10];
    const float* d0_Whh  = (const float*)d_in[11];
    const float* d0_b    = (const float*)d_in[12];
    const float* d1_Wih  = (const float*)d_in[13];
    const float* d1_Whh  = (const float*)d_in[14];
    const float* d1_b    = (const float*)d_in[15];
    const float* lin_W   = (const float*)d_in[16];
    const float* lin_b   = (const float*)d_in[17];
    float* out = (float*)d_out;

    float *xs, *preE, *preD, *u2;
    cudaGetSymbolAddress((void**)&xs,   g_xs);
    cudaGetSymbolAddress((void**)&preE, g_preE);
    cudaGetSymbolAddress((void**)&preD, g_preD);
    cudaGetSymbolAddress((void**)&u2,   g_u2);

    cudaFuncSetAttribute(k_merged, cudaFuncAttributeMaxDynamicSharedMemorySize, FSMEM);
    cudaFuncSetAttribute(k_mmagemm<0>, cudaFuncAttributeMaxDynamicSharedMemorySize, GSMEM);
    cudaFuncSetAttribute(k_mmagemm<1>, cudaFuncAttributeMaxDynamicSharedMemorySize, GSMEM);

    dim3 gg(16, 16), gp(16, VOC / 128);

    k_zero<<<64, 256>>>();

    // both input GEMMs up front (decoder path independent of encoder)
    k_embed<<<M2, 128>>>(x, tgt, enc_emb, xs, 0);
    k_mmagemm<0><<<gg, 256, GSMEM>>>(xs, e0_Wih, e0_b, preE, G4);
    k_embed<<<M2, 128>>>(x, tgt, dec_emb, xs, 1);
    k_mmagemm<0><<<gg, 256, GSMEM>>>(xs, d0_Wih, d0_b, preD, G4);

    // single 129-round wavefront: enc L0/L1 -> dec L0/L1, states in registers
    k_merged<<<RB, FT, FSMEM>>>(preE, preD, e0_Whh, e1_Wih, e1_Whh, e1_b,
                                d0_Whh, d1_Wih, d1_Whh, d1_b, u2);

    // projection
    k_mmagemm<1><<<gp, 256, GSMEM>>>(u2, lin_W, lin_b, out, VOC);
}

// round 11
// speedup vs baseline: 2.9954x; 1.0110x over previous
#include <cuda_runtime.h>
#include <cuda_bf16.h>
#include <math.h>
#include <stdint.h>

#define BSZ   32
#define TLEN  64
#define ED    512
#define HD    512
#define G4    2048
#define M2    2048
#define VOC   32000
#define RB    128

// ---------------- scratch (device globals; no allocation) ----------------
__device__ float    g_preE[M2 * G4];
__device__ float    g_preD[M2 * G4];
__device__ uint16_t g_xsh[M2 * ED], g_xsl[M2 * ED];     // packed inputs
__device__ uint16_t g_wh [G4 * ED], g_wl [G4 * ED];     // packed Wih (reused)
__device__ uint16_t g_lwh[VOC * ED], g_lwl[VOC * ED];   // packed lin_W
__device__ uint16_t g_u2h[M2 * HD], g_u2l[M2 * HD];     // packed u2 (from merged)
__device__ uint32_t g_hq[2][2][2][8192];
__device__ __align__(16) unsigned g_flags2[RB * 32];

// ================= helpers =================
__device__ __forceinline__ uint32_t smem_u32(const void* p) {
    uint32_t a;
    asm("{ .reg .u64 t; cvta.to.shared.u64 t, %1; cvt.u32.u64 %0, t; }" : "=r"(a) : "l"(p));
    return a;
}
__device__ __forceinline__ float fsig(float x) {
    return __fdividef(1.f, 1.f + __expf(-x));
}
__device__ __forceinline__ float ftanh(float x) {
    return 1.f - __fdividef(2.f, __expf(2.f * x) + 1.f);
}

#define LDMX4(r0, r1, r2, r3, a) \
    asm volatile("ldmatrix.sync.aligned.m8n8.x4.shared.b16 {%0,%1,%2,%3}, [%4];" \
        : "=r"(r0), "=r"(r1), "=r"(r2), "=r"(r3) : "r"(a))

#define LDMX4T(r0, r1, r2, r3, a) \
    asm volatile("ldmatrix.sync.aligned.m8n8.x4.trans.shared.b16 {%0,%1,%2,%3}, [%4];" \
        : "=r"(r0), "=r"(r1), "=r"(r2), "=r"(r3) : "r"(a))

#define STS128(a, r0, r1, r2, r3) \
    asm volatile("st.shared.v4.b32 [%0], {%1,%2,%3,%4};" \
        :: "r"(a), "r"(r0), "r"(r1), "r"(r2), "r"(r3) : "memory")

__device__ __forceinline__ void mma16816(float* d, const uint32_t* a, const uint32_t* b) {
    asm volatile("mma.sync.aligned.m16n8k16.row.col.f32.bf16.bf16.f32 "
        "{%0,%1,%2,%3},{%4,%5,%6,%7},{%8,%9},{%0,%1,%2,%3};"
        : "+f"(d[0]), "+f"(d[1]), "+f"(d[2]), "+f"(d[3])
        : "r"(a[0]), "r"(a[1]), "r"(a[2]), "r"(a[3]), "r"(b[0]), "r"(b[1]));
}

__device__ __forceinline__ void cvt2(float x, float y, uint32_t& hi, uint32_t& lo) {
    asm("cvt.rn.bf16x2.f32 %0, %1, %2;" : "=r"(hi) : "f"(y), "f"(x));
    float rx = x - __uint_as_float(hi << 16);
    float ry = y - __uint_as_float(hi & 0xFFFF0000u);
    asm("cvt.rn.bf16x2.f32 %0, %1, %2;" : "=r"(lo) : "f"(ry), "f"(rx));
}

// ---------------- pack fp32 -> bf16 hi/lo planes ----------------
__global__ void k_pack(const float* __restrict__ src,
                       uint16_t* __restrict__ hi, uint16_t* __restrict__ lo) {
    size_t base = ((size_t)blockIdx.x * 256 + threadIdx.x) * 8;
    float4 a = *(const float4*)(src + base);
    float4 b = *(const float4*)(src + base + 4);
    uint32_t h[4], l[4];
    cvt2(a.x, a.y, h[0], l[0]); cvt2(a.z, a.w, h[1], l[1]);
    cvt2(b.x, b.y, h[2], l[2]); cvt2(b.z, b.w, h[3], l[3]);
    *(uint4*)(hi + base) = make_uint4(h[0], h[1], h[2], h[3]);
    *(uint4*)(lo + base) = make_uint4(l[0], l[1], l[2], l[3]);
}

// ================= split-bf16 HMMA GEMM, pre-packed operands =================
// smem per stage: A_hi 0 / A_lo 10240 / B_hi 20480 / B_lo 30720 (80B rows)
#define STAGE  40960
#define GSMEM  81920

template<int PERM>
__global__ void __launch_bounds__(256, 1)
k_gemm_q(const uint16_t* __restrict__ Ah, const uint16_t* __restrict__ Al,
         const uint16_t* __restrict__ Bh, const uint16_t* __restrict__ Bl,
         const float* __restrict__ bias, float* __restrict__ C, int ldc) {
    extern __shared__ char smx[];
    uint32_t sb = smem_u32(smx);
    int tid = threadIdx.x, lid = tid & 31, wid = tid >> 5;
    int wm = wid >> 2, wn = wid & 3;
    int rb = blockIdx.x * 128, cb = blockIdx.y * 128;

    const uint8_t* planes[4] = {(const uint8_t*)Ah, (const uint8_t*)Al,
                                (const uint8_t*)Bh, (const uint8_t*)Bl};

    // staging: i-th batch -> plane i>>1? (planes 0..3 over i 0..7: plane = i>>1)
    uint4 v[8];
    #pragma unroll
    for (int i = 0; i < 8; i++) {
        int plane = i >> 1, idx = (i & 1) * 256 + tid;
        int row = ((plane < 2) ? rb : cb) + (idx >> 2);
        v[i] = *(const uint4*)(planes[plane] + (size_t)row * 1024 + (idx & 3) * 16);
    }
    #pragma unroll
    for (int i = 0; i < 8; i++) {
        int plane = i >> 1, idx = (i & 1) * 256 + tid;
        STS128(sb + plane * 10240 + (idx >> 2) * 80 + (idx & 3) * 16,
               v[i].x, v[i].y, v[i].z, v[i].w);
    }
    __syncthreads();

    uint32_t abase = sb + (uint32_t)(wm * 64 + (lid & 15)) * 80 + (lid >> 4) * 16;
    uint32_t bbase = sb + 20480 + (uint32_t)(wn * 32 + (lid & 15)) * 80 + (lid >> 4) * 16;

    float acc[4][4][4] = {};

    for (int c = 0; c < 16; c++) {
        if (c < 15) {
            #pragma unroll
            for (int i = 0; i < 8; i++) {
                int plane = i >> 1, idx = (i & 1) * 256 + tid;
                int row = ((plane < 2) ? rb : cb) + (idx >> 2);
                v[i] = *(const uint4*)(planes[plane] + (size_t)row * 1024
                                       + (c + 1) * 64 + (idx & 3) * 16);
            }
        }
        uint32_t so = (uint32_t)(c & 1) * STAGE;
        #pragma unroll
        for (int ks = 0; ks < 2; ks++) {
            uint32_t ah[4][4], al[4][4], bh[4][2], bl[4][2];
            #pragma unroll
            for (int ma = 0; ma < 4; ma++) {
                uint32_t ad = abase + so + (uint32_t)(ma * 16 * 80 + ks * 32);
                LDMX4(ah[ma][0], ah[ma][1], ah[ma][2], ah[ma][3], ad);
                LDMX4(al[ma][0], al[ma][1], al[ma][2], al[ma][3], ad + 10240);
            }
            #pragma unroll
            for (int p = 0; p < 2; p++) {
                uint32_t bd = bbase + so + (uint32_t)(p * 16 * 80 + ks * 32);
                uint32_t m0, m1, m2, m3;
                LDMX4(m0, m1, m2, m3, bd);
                bh[2*p][0] = m0; bh[2*p][1] = m2; bh[2*p+1][0] = m1; bh[2*p+1][1] = m3;
                LDMX4(m0, m1, m2, m3, bd + 10240);
                bl[2*p][0] = m0; bl[2*p][1] = m2; bl[2*p+1][0] = m1; bl[2*p+1][1] = m3;
            }
            #pragma unroll
            for (int ma = 0; ma < 4; ma++)
                #pragma unroll
                for (int na = 0; na < 4; na++) {
                    mma16816(acc[ma][na], ah[ma], bh[na]);
                    mma16816(acc[ma][na], ah[ma], bl[na]);
                    mma16816(acc[ma][na], al[ma], bh[na]);
                }
        }
        if (c < 15) {
            uint32_t so2 = (uint32_t)((c + 1) & 1) * STAGE;
            #pragma unroll
            for (int i = 0; i < 8; i++) {
                int plane = i >> 1, idx = (i & 1) * 256 + tid;
                STS128(sb + so2 + plane * 10240 + (idx >> 2) * 80 + (idx & 3) * 16,
                       v[i].x, v[i].y, v[i].z, v[i].w);
            }
        }
        __syncthreads();
    }

    #pragma unroll
    for (int ma = 0; ma < 4; ma++) {
        int m  = rb + wm * 64 + ma * 16 + (lid >> 2);
        int m2 = m + 8;
        size_t ro0 = PERM ? (size_t)((m  & 31) * TLEN + (m  >> 5)) : (size_t)m;
        size_t ro1 = PERM ? (size_t)((m2 & 31) * TLEN + (m2 >> 5)) : (size_t)m2;
        #pragma unroll
        for (int na = 0; na < 4; na++) {
            int c0 = cb + wn * 32 + na * 8 + (lid & 3) * 2;
            float2 bv = *(const float2*)(bias + c0);
            float* a = acc[ma][na];
            *(float2*)(C + ro0 * (size_t)ldc + c0) = make_float2(a[0] + bv.x, a[1] + bv.y);
            *(float2*)(C + ro1 * (size_t)ldc + c0) = make_float2(a[2] + bv.x, a[3] + bv.y);
        }
    }
}

// ---------------- zero h state ----------------
__global__ void k_zero() {
    int i = blockIdx.x * 256 + threadIdx.x;
    ((uint4*)g_hq)[i] = make_uint4(0u, 0u, 0u, 0u);
}

// ---------------- embedding gather, packed output ----------------
__global__ void k_embed(const int* __restrict__ toks, const int* __restrict__ tgt,
                        const float* __restrict__ emb,
                        uint16_t* __restrict__ xh, uint16_t* __restrict__ xl, int dec) {
    int row = blockIdx.x;
    int t = row >> 5, b = row & 31;
    int tok;
    if (dec) tok = (t == 0) ? 1 : tgt[b * TLEN + t - 1];
    else     tok = toks[b * TLEN + t];
    float4 f = ((const float4*)(emb + (size_t)tok * ED))[threadIdx.x];
    uint32_t h0, l0, h1, l1;
    cvt2(f.x, f.y, h0, l0);
    cvt2(f.z, f.w, h1, l1);
    *(uint2*)(xh + (size_t)row * ED + threadIdx.x * 4) = make_uint2(h0, h1);
    *(uint2*)(xl + (size_t)row * ED + threadIdx.x * 4) = make_uint2(l0, l1);
}

// ================= merged 129-round enc+dec wavefront (R10, u2 packed) =====
#define FT      384
#define HROW    80
#define PARTOFF 163840
#define PSTR    36
#define USTR    2304
#define FSMEM   (163840 + 27648)

__device__ __forceinline__ void load_wfrag(const float* wbase, int jA, int jB,
                                           int kq, int kc,
                                           uint32_t ahi[8][4], uint32_t alo[8][4]) {
    #pragma unroll
    for (int kt = 0; kt < 8; kt++) {
        int k0 = kq * 128 + kt * 16 + kc;
        float2 w00 = *(const float2*)(wbase + (size_t)jA * 512 + k0);
        float2 w10 = *(const float2*)(wbase + (size_t)jB * 512 + k0);
        float2 w01 = *(const float2*)(wbase + (size_t)jA * 512 + k0 + 8);
        float2 w11 = *(const float2*)(wbase + (size_t)jB * 512 + k0 + 8);
        cvt2(w00.x, w00.y, ahi[kt][0], alo[kt][0]);
        cvt2(w10.x, w10.y, ahi[kt][1], alo[kt][1]);
        cvt2(w01.x, w01.y, ahi[kt][2], alo[kt][2]);
        cvt2(w11.x, w11.y, ahi[kt][3], alo[kt][3]);
    }
}

__global__ void __launch_bounds__(FT, 1)
k_merged(const float* __restrict__ preE, const float* __restrict__ preD,
         const float* __restrict__ e0_Whh, const float* __restrict__ e1_Wih,
         const float* __restrict__ e1_Whh, const float* __restrict__ e1_b,
         const float* __restrict__ d0_Whh, const float* __restrict__ d1_Wih,
         const float* __restrict__ d1_Whh, const float* __restrict__ d1_b,
         uint16_t* __restrict__ youth, uint16_t* __restrict__ youtl) {
    extern __shared__ char smc[];
    uint32_t sb = smem_u32(smc);
    float* part = (float*)(smc + PARTOFF);

    int tid = threadIdx.x, bl = blockIdx.x;
    int wid = tid >> 5, l = tid & 31;
    int sec = wid >> 2, kq = wid & 3;

    const float* w_e = (sec == 0) ? e0_Whh : (sec == 1) ? e1_Wih : e1_Whh;
    const float* w_d = (sec == 0) ? d0_Whh : (sec == 1) ? d1_Wih : d1_Whh;
    int wswitch = (sec == 0) ? 64 : 65;

    int rA = l >> 2, rB = rA + 8;
    int jA = (rA >> 2) * 512 + bl * 4 + (rA & 3);
    int jB = (rB >> 2) * 512 + bl * 4 + (rB & 3);
    int kc = (l & 3) * 2;
    uint32_t ahi[8][4], alo[8][4];
    load_wfrag(w_e, jA, jB, kq, kc, ahi, alo);

    int krow = (l & 7) + ((l & 8) ? 8 : 0);
    int ncol = (l & 16) ? 8 : 0;
    uint32_t hbase = sb + ((sec == 2) ? 81920u : 0u)
                   + (uint32_t)(kq * 128 + krow) * HROW + ncol * 2;

    float* myp = part + sec * USTR + kq * 576;

    int stid = tid & 127;
    int m_l = stid >> 5, eb = stid & 31;
    int m_g = bl * 4 + m_l;
    float biasE[4], biasD[4];
    #pragma unroll
    for (int g = 0; g < 4; g++) {
        biasE[g] = e1_b[g * 512 + bl * 4 + m_l];
        biasD[g] = d1_b[g * 512 + bl * 4 + m_l];
    }

    unsigned base = *((volatile unsigned*)&g_flags2[bl * 32]);

    float c0_reg = 0.f, c1_reg = 0.f;

    for (int tau = 0; tau <= 2 * TLEN; tau++) {
        int doL0 = (tau < 2 * TLEN), doL1 = (tau >= 1);

        float pp[4];
        if (sec == 0 && doL0) {
            const float* p = (tau < 64) ? preE : preD;
            int step = (tau < 64) ? tau : tau - 64;
            #pragma unroll
            for (int g = 0; g < 4; g++)
                pp[g] = p[(size_t)(step * 32 + eb) * G4 + g * 512 + bl * 4 + m_l];
        }

        {
            const uint4* s0 = (const uint4*)(&g_hq[0][tau & 1][0][0]);
            const uint4* s1 = (const uint4*)(&g_hq[1][tau & 1][0][0]);
            #pragma unroll
            for (int i = 0; i < 22; i++) {
                int lin = tid + i * FT;
                if (lin < 8192) {
                    uint4 v = __ldcg((lin < 4096 ? s0 : s1) + (lin & 4095));
                    uint32_t ad = sb + (uint32_t)(lin >> 11) * 40960u
                                + (uint32_t)((lin & 2047) >> 2) * HROW
                                + (uint32_t)(lin & 3) * 16u;
                    STS128(ad, v.x, v.y, v.z, v.w);
                }
            }
        }
        __syncthreads();

        int active = (sec == 0) ? doL0 : doL1;
        if (active) {
            float acc[4][4];
            #pragma unroll
            for (int i = 0; i < 4; i++)
                #pragma unroll
                for (int q = 0; q < 4; q++) acc[i][q] = 0.f;
            #pragma unroll
            for (int kt = 0; kt < 8; kt++) {
                uint32_t ka = hbase + (uint32_t)(kt * 16) * HROW;
                uint32_t bh[4][2], bl2[4][2];
                #pragma unroll
                for (int nbp = 0; nbp < 2; nbp++) {
                    uint32_t m0, m1, m2, m3;
                    LDMX4T(m0, m1, m2, m3, ka + nbp * 32);
                    bh[2*nbp][0] = m0; bh[2*nbp][1] = m1;
                    bh[2*nbp+1][0] = m2; bh[2*nbp+1][1] = m3;
                    LDMX4T(m0, m1, m2, m3, ka + nbp * 32 + 40960);
                    bl2[2*nbp][0] = m0; bl2[2*nbp][1] = m1;
                    bl2[2*nbp+1][0] = m2; bl2[2*nbp+1][1] = m3;
                }
                #pragma unroll
                for (int nt = 0; nt < 4; nt++) {
                    mma16816(acc[nt], ahi[kt], bh[nt]);
                    mma16816(acc[nt], ahi[kt], bl2[nt]);
                    mma16816(acc[nt], alo[kt], bh[nt]);
                }
            }
            #pragma unroll
            for (int nt = 0; nt < 4; nt++) {
                int c = nt * 8 + kc;
                *(float2*)(myp + rA * PSTR + c) = make_float2(acc[nt][0], acc[nt][1]);
                *(float2*)(myp + rB * PSTR + c) = make_float2(acc[nt][2], acc[nt][3]);
            }
        }
        __syncthreads();

        if (sec == 0 && doL0) {
            float gv4[4];
            #pragma unroll
            for (int g = 0; g < 4; g++) {
                int o = (g * 4 + m_l) * PSTR + eb;
                gv4[g] = pp[g] + part[o] + part[576 + o] + part[1152 + o] + part[1728 + o];
            }
            c0_reg = fsig(gv4[1]) * c0_reg + fsig(gv4[0]) * ftanh(gv4[2]);
            float h = fsig(gv4[3]) * ftanh(c0_reg);
            float hot = __shfl_xor_sync(0xFFFFFFFFu, h, 1);
            if (!(eb & 1)) {
                uint32_t hi, lo;
                cvt2(h, hot, hi, lo);
                int idx = m_g * 16 + (eb >> 1);
                g_hq[0][(tau + 1) & 1][0][idx] = hi;
                g_hq[0][(tau + 1) & 1][1][idx] = lo;
            }
        }
        float h1v = 0.f;
        if (sec == 1 && doL1) {
            float gv4[4];
            #pragma unroll
            for (int g = 0; g < 4; g++) {
                int o = (g * 4 + m_l) * PSTR + eb;
                float s = (tau >= 65) ? biasD[g] : biasE[g];
                #pragma unroll
                for (int w = 0; w < 4; w++)
                    s += part[USTR + w * 576 + o] + part[2 * USTR + w * 576 + o];
                gv4[g] = s;
            }
            c1_reg = fsig(gv4[1]) * c1_reg + fsig(gv4[0]) * ftanh(gv4[2]);
            h1v = fsig(gv4[3]) * ftanh(c1_reg);
            float hot = __shfl_xor_sync(0xFFFFFFFFu, h1v, 1);
            if (!(eb & 1)) {
                uint32_t hi, lo;
                cvt2(h1v, hot, hi, lo);
                int idx = m_g * 16 + (eb >> 1);
                g_hq[1][(tau - 1) & 1][0][idx] = hi;
                g_hq[1][(tau - 1) & 1][1][idx] = lo;
            }
        }
        __syncthreads();

        if (tid == 0)
            asm volatile("st.release.gpu.global.u32 [%0], %1;"
                :: "l"(g_flags2 + bl * 32), "r"(base + tau + 1) : "memory");
        // off-critical-path: packed u2 store + d-weight reload
        if (sec == 1 && tau >= 65) {
            uint32_t hw, lw;
            cvt2(h1v, 0.f, hw, lw);
            size_t o = (size_t)((tau - 65) * 32 + eb) * HD + m_g;
            youth[o] = (uint16_t)hw;
            youtl[o] = (uint16_t)lw;
        }
        if (tau + 1 == wswitch)
            load_wfrag(w_d, jA, jB, kq, kc, ahi, alo);
        if (tid < 32) {
            unsigned tg = base + tau + 1;
            for (;;) {
                unsigned v0, v1, v2, v3;
                asm volatile("ld.acquire.gpu.global.u32 %0, [%1];" : "=r"(v0)
                    : "l"(g_flags2 + l * 32));
                asm volatile("ld.acquire.gpu.global.u32 %0, [%1];" : "=r"(v1)
                    : "l"(g_flags2 + (l + 32) * 32));
                asm volatile("ld.acquire.gpu.global.u32 %0, [%1];" : "=r"(v2)
                    : "l"(g_flags2 + (l + 64) * 32));
                asm volatile("ld.acquire.gpu.global.u32 %0, [%1];" : "=r"(v3)
                    : "l"(g_flags2 + (l + 96) * 32));
                int ok = ((int)(v0 - tg) >= 0) & ((int)(v1 - tg) >= 0) &
                         ((int)(v2 - tg) >= 0) & ((int)(v3 - tg) >= 0);
                if (__all_sync(0xFFFFFFFFu, ok)) break;
            }
        }
        __syncthreads();
    }
}

// ---------------- launcher ----------------
extern "C" void kernel_launch(void* const* d_in, const int* in_sizes, int n_in,
                              void* d_out, int out_size) {
    const int*   x       = (const int*)  d_in[0];
    const int*   tgt     = (const int*)  d_in[1];
    const float* enc_emb = (const float*)d_in[2];
    const float* dec_emb = (const float*)d_in[3];
    const float* e0_Wih  = (const float*)d_in[4];
    const float* e0_Whh  = (const float*)d_in[5];
    const float* e0_b    = (const float*)d_in[6];
    const float* e1_Wih  = (const float*)d_in[7];
    const float* e1_Whh  = (const float*)d_in[8];
    const float* e1_b    = (const float*)d_in[9];
    const float* d0_Wih  = (const float*)d_in[10];
    const float* d0_Whh  = (const float*)d_in[11];
    const float* d0_b    = (const float*)d_in[12];
    const float* d1_Wih  = (const float*)d_in[13];
    const float* d1_Whh  = (const float*)d_in[14];
    const float* d1_b    = (const float*)d_in[15];
    const float* lin_W   = (const float*)d_in[16];
    const float* lin_b   = (const float*)d_in[17];
    float* out = (float*)d_out;

    float *preE, *preD;
    uint16_t *xsh, *xsl, *wh, *wl, *lwh, *lwl, *u2h, *u2l;
    cudaGetSymbolAddress((void**)&preE, g_preE);
    cudaGetSymbolAddress((void**)&preD, g_preD);
    cudaGetSymbolAddress((void**)&xsh,  g_xsh);
    cudaGetSymbolAddress((void**)&xsl,  g_xsl);
    cudaGetSymbolAddress((void**)&wh,   g_wh);
    cudaGetSymbolAddress((void**)&wl,   g_wl);
    cudaGetSymbolAddress((void**)&lwh,  g_lwh);
    cudaGetSymbolAddress((void**)&lwl,  g_lwl);
    cudaGetSymbolAddress((void**)&u2h,  g_u2h);
    cudaGetSymbolAddress((void**)&u2l,  g_u2l);

    cudaFuncSetAttribute(k_merged, cudaFuncAttributeMaxDynamicSharedMemorySize, FSMEM);
    cudaFuncSetAttribute(k_gemm_q<0>, cudaFuncAttributeMaxDynamicSharedMemorySize, GSMEM);
    cudaFuncSetAttribute(k_gemm_q<1>, cudaFuncAttributeMaxDynamicSharedMemorySize, GSMEM);

    dim3 gg(16, 16), gp(16, VOC / 128);

    k_zero<<<64, 256>>>();

    // encoder L0 input path
    k_embed<<<M2, 128>>>(x, tgt, enc_emb, xsh, xsl, 0);
    k_pack<<<(G4 * ED) / 2048, 256>>>(e0_Wih, wh, wl);
    k_gemm_q<0><<<gg, 256, GSMEM>>>(xsh, xsl, wh, wl, e0_b, preE, G4);

    // decoder L0 input path
    k_embed<<<M2, 128>>>(x, tgt, dec_emb, xsh, xsl, 1);
    k_pack<<<(G4 * ED) / 2048, 256>>>(d0_Wih, wh, wl);
    k_gemm_q<0><<<gg, 256, GSMEM>>>(xsh, xsl, wh, wl, d0_b, preD, G4);

    // pack projection weights
    k_pack<<<(VOC * ED) / 2048, 256>>>(lin_W, lwh, lwl);

    // merged 129-round wavefront (produces packed u2)
    k_merged<<<RB, FT, FSMEM>>>(preE, preD, e0_Whh, e1_Wih, e1_Whh, e1_b,
                                d0_Whh, d1_Wih, d1_Whh, d1_b, u2h, u2l);

    // projection
    k_gemm_q<1><<<gp, 256, GSMEM>>>(u2h, u2l, lwh, lwl, lin_b, out, VOC);
}